// round 12
// baseline (speedup 1.0000x reference)
#include <cuda_runtime.h>
#include <cuda_fp16.h>
#include <math.h>
#include <cstdint>

#define BATCH 4
#define NQ 4096
#define NL 1024
#define DV 512
#define DC 128
#define DI 512
#define DF 2048
#define NH 8
#define HD 64

// ---------------- device scratch ----------------
__device__ float g_vk [BATCH * NL * (2 * DI)];
__device__ float g_kc [BATCH * NL * DI];
__device__ float g_qv [BATCH * NQ * DI];
__device__ float g_qc [BATCH * NQ * DI];
__device__ float g_y  [BATCH * NQ * DV];
__device__ __align__(16) __half g_qvh[BATCH * NQ * DI], g_qch[BATCH * NQ * DI];
__device__ __align__(16) __half g_kf [BATCH * NH * NL * 128];   // [bh][j][kc|lam*kv]
__device__ __align__(16) __half g_vt [BATCH * NH * 64 * NL];    // [bh][d][j]
__device__ __align__(16) __half g_sLv_h[BATCH * NL * DV], g_sLv_l[BATCH * NL * DV];
__device__ __align__(16) __half g_sLc_h[BATCH * NL * DC], g_sLc_l[BATCH * NL * DC];
__device__ __align__(16) __half g_val_h[BATCH * NQ * DV], g_val_l[BATCH * NQ * DV];
__device__ __align__(16) __half g_crd_h[BATCH * NQ * DC], g_crd_l[BATCH * NQ * DC];
__device__ __align__(16) __half g_att_h[BATCH * NQ * DI];
__device__ __align__(16) __half g_ybs_h[BATCH * NQ * DV], g_ybs_l[BATCH * NQ * DV];
__device__ __align__(16) __half g_h1_h[BATCH * NQ * DF];
__device__ __align__(16) __half g_h2_h[BATCH * NQ * DF];
__device__ __align__(16) __half g_wth[7471104], g_wtl[7471104];

#define OFF_CKW 0
#define OFF_CQW 65536
#define OFF_VQW 131072
#define OFF_VKW 393216
#define OFF_OPW 917504
#define OFF_M1W 1179648
#define OFF_M2W 2228224
#define OFF_M3W 6422528

// ---------------- helpers ----------------
__device__ __forceinline__ float gelu_f(float x) {
    float x3 = x * x * x;
    return 0.5f * x * (1.0f + tanhf(0.7978845608028654f * (x + 0.044715f * x3)));
}
__device__ __forceinline__ void split2h(float x, __half& h, __half& l) {
    h = __float2half_rn(x);
    l = __float2half_rn(x - __half2float(h));
}
__device__ __forceinline__ void mma_f16(float* c, const unsigned* a, unsigned b0, unsigned b1) {
    asm volatile(
        "mma.sync.aligned.m16n8k16.row.col.f32.f16.f16.f32 "
        "{%0,%1,%2,%3},{%4,%5,%6,%7},{%8,%9},{%0,%1,%2,%3};"
        : "+f"(c[0]), "+f"(c[1]), "+f"(c[2]), "+f"(c[3])
        : "r"(a[0]), "r"(a[1]), "r"(a[2]), "r"(a[3]), "r"(b0), "r"(b1));
}
__device__ __forceinline__ void ldsm4(unsigned* r, unsigned addr) {
    asm volatile("ldmatrix.sync.aligned.m8n8.x4.shared.b16 {%0,%1,%2,%3}, [%4];"
        : "=r"(r[0]), "=r"(r[1]), "=r"(r[2]), "=r"(r[3]) : "r"(addr));
}
__device__ __forceinline__ void cpa16(unsigned dst, const void* src) {
    asm volatile("cp.async.cg.shared.global [%0], [%1], 16;" :: "r"(dst), "l"(src));
}
__device__ __forceinline__ void cpa_commit() { asm volatile("cp.async.commit_group;"); }
__device__ __forceinline__ unsigned sh_addr(const void* p) {
    return (unsigned)__cvta_generic_to_shared(p);
}

// ---------------- producers ----------------
__global__ void split_copy_h(const float* __restrict__ x, __half* __restrict__ h,
                             __half* __restrict__ l, int n4) {
    int i = blockIdx.x * blockDim.x + threadIdx.x;
    if (i < n4) {
        float4 v = ((const float4*)x)[i];
        int b = i * 4;
        __half h0, l0; split2h(v.x, h0, l0); h[b] = h0; l[b] = l0;
        split2h(v.y, h0, l0); h[b+1] = h0; l[b+1] = l0;
        split2h(v.z, h0, l0); h[b+2] = h0; l[b+2] = l0;
        split2h(v.w, h0, l0); h[b+3] = h0; l[b+3] = l0;
    }
}

// batched weight split+transpose (subset of up to 8 layers per launch)
struct WsArgs {
    const float* W[8];
    __half* th[8];
    __half* tl[8];
    int K[8], N[8];
    int start[9];
};
__global__ void wtsplit_all(WsArgs a) {
    __shared__ float t[32][33];
    int bid = blockIdx.x;
    int l = 0;
    #pragma unroll
    for (int i = 1; i < 8; i++) if (bid >= a.start[i]) l = i;
    int tidx = bid - a.start[l];
    int K = a.K[l], N = a.N[l];
    int ntn = N >> 5;
    int k0 = (tidx / ntn) << 5;
    int n0 = (tidx % ntn) << 5;
    const float* W = a.W[l];
    __half* th = a.th[l];
    __half* tl = a.tl[l];
    int tx = threadIdx.x, ty = threadIdx.y;
    for (int dy = ty; dy < 32; dy += 8)
        t[dy][tx] = W[(size_t)(k0 + dy) * N + n0 + tx];
    __syncthreads();
    for (int rr = ty; rr < 32; rr += 8) {
        __half h, lo; split2h(t[tx][rr], h, lo);
        th[(size_t)(n0 + rr) * K + k0 + tx] = h;
        tl[(size_t)(n0 + rr) * K + k0 + tx] = lo;
    }
}

__global__ void layernorm_split(const float* __restrict__ x, const float* __restrict__ g,
                                const float* __restrict__ b, __half* __restrict__ yh,
                                __half* __restrict__ yl, int D, float eps) {
    int row = blockIdx.x;
    const float* xr = x + (size_t)row * D;
    float s = 0.f, ss = 0.f;
    for (int i = threadIdx.x; i < D; i += blockDim.x) { float v = xr[i]; s += v; ss += v * v; }
    __shared__ float rs[32], rss[32];
    #pragma unroll
    for (int off = 16; off; off >>= 1) {
        s  += __shfl_xor_sync(0xffffffffu, s,  off);
        ss += __shfl_xor_sync(0xffffffffu, ss, off);
    }
    int w = threadIdx.x >> 5, l = threadIdx.x & 31;
    if (l == 0) { rs[w] = s; rss[w] = ss; }
    __syncthreads();
    int nw = blockDim.x >> 5;
    if (threadIdx.x < 32) {
        s  = (l < nw) ? rs[l]  : 0.f;
        ss = (l < nw) ? rss[l] : 0.f;
        #pragma unroll
        for (int off = 16; off; off >>= 1) {
            s  += __shfl_xor_sync(0xffffffffu, s,  off);
            ss += __shfl_xor_sync(0xffffffffu, ss, off);
        }
        if (l == 0) { rs[0] = s; rss[0] = ss; }
    }
    __syncthreads();
    float mean = rs[0] / (float)D;
    float inv  = rsqrtf(rss[0] / (float)D - mean * mean + eps);
    for (int i = threadIdx.x; i < D; i += blockDim.x) {
        __half h, lo; split2h((xr[i] - mean) * inv * g[i] + b[i], h, lo);
        yh[(size_t)row * D + i] = h; yl[(size_t)row * D + i] = lo;
    }
}

__global__ void rmsnorm_kernel(float* __restrict__ x, const float* __restrict__ g,
                               int D, float eps, float scale) {
    int row = blockIdx.x;
    float* xr = x + (size_t)row * D;
    float ss = 0.f;
    for (int i = threadIdx.x; i < D; i += blockDim.x) { float v = xr[i]; ss += v * v; }
    __shared__ float rss[32];
    #pragma unroll
    for (int off = 16; off; off >>= 1) ss += __shfl_xor_sync(0xffffffffu, ss, off);
    int w = threadIdx.x >> 5, l = threadIdx.x & 31;
    if (l == 0) rss[w] = ss;
    __syncthreads();
    int nw = blockDim.x >> 5;
    if (threadIdx.x < 32) {
        ss = (l < nw) ? rss[l] : 0.f;
        #pragma unroll
        for (int off = 16; off; off >>= 1) ss += __shfl_xor_sync(0xffffffffu, ss, off);
        if (l == 0) rss[0] = ss;
    }
    __syncthreads();
    float inv = rsqrtf(rss[0] / (float)D + eps) * scale;
    for (int i = threadIdx.x; i < D; i += blockDim.x)
        xr[i] = xr[i] * inv * g[i];
}

__global__ void rmsnorm_h(const float* __restrict__ x, const float* __restrict__ g,
                          __half* __restrict__ y, int D, float eps, float scale) {
    int row = blockIdx.x;
    const float* xr = x + (size_t)row * D;
    float ss = 0.f;
    for (int i = threadIdx.x; i < D; i += blockDim.x) { float v = xr[i]; ss += v * v; }
    __shared__ float rss[32];
    #pragma unroll
    for (int off = 16; off; off >>= 1) ss += __shfl_xor_sync(0xffffffffu, ss, off);
    int w = threadIdx.x >> 5, l = threadIdx.x & 31;
    if (l == 0) rss[w] = ss;
    __syncthreads();
    int nw = blockDim.x >> 5;
    if (threadIdx.x < 32) {
        ss = (l < nw) ? rss[l] : 0.f;
        #pragma unroll
        for (int off = 16; off; off >>= 1) ss += __shfl_xor_sync(0xffffffffu, ss, off);
        if (l == 0) rss[0] = ss;
    }
    __syncthreads();
    float inv = rsqrtf(rss[0] / (float)D + eps) * scale;
    for (int i = threadIdx.x; i < D; i += blockDim.x)
        y[(size_t)row * D + i] = __float2half_rn(xr[i] * inv * g[i]);
}

__global__ void kcomb_kernel(const float* __restrict__ kc, const float* __restrict__ vk,
                             const float* __restrict__ lamp, __half* __restrict__ kf) {
    int j = blockIdx.x, b = blockIdx.y;
    int tid = threadIdx.x;
    float lam = lamp[0];
    int e = tid * 4;
    int h = e >> 7, dd = e & 127;
    float4 v;
    if (dd < 64)
        v = *(const float4*)&kc[((size_t)(b * NL + j)) * DI + h * 64 + dd];
    else {
        v = *(const float4*)&vk[((size_t)(b * NL + j)) * (2 * DI) + DI + h * 64 + (dd - 64)];
        v.x *= lam; v.y *= lam; v.z *= lam; v.w *= lam;
    }
    __half* dst = kf + ((size_t)((b * NH + h) * NL + j)) * 128 + dd;
    dst[0] = __float2half_rn(v.x); dst[1] = __float2half_rn(v.y);
    dst[2] = __float2half_rn(v.z); dst[3] = __float2half_rn(v.w);
}

__global__ void vtrans_kernel(const float* __restrict__ vk, __half* __restrict__ vt) {
    __shared__ float t[32][33];
    int bh = blockIdx.z; int b = bh >> 3; int h = bh & 7;
    int j0 = blockIdx.x * 32, d0 = blockIdx.y * 32;
    int tx = threadIdx.x, ty = threadIdx.y;
    const float* s = vk + ((size_t)(b * NL + j0)) * (2 * DI) + h * HD + d0;
    for (int dy = ty; dy < 32; dy += 8)
        t[dy][tx] = s[(size_t)dy * (2 * DI) + tx];
    __syncthreads();
    for (int dy = ty; dy < 32; dy += 8)
        vt[((size_t)(bh * 64 + d0 + dy)) * NL + j0 + tx] = __float2half_rn(t[tx][dy]);
}

// ---------------- fp16 GEMM 128x128x32, 3-stage, 8 warps (warp tile 32x64) ----------------
#define RSTR 40
#define PLANE_B (128 * RSTR * 2)  // 10240
template <int EPI, bool COMP>    // EPI: 0=bias fp32, 1=bias+gelu fp16
__global__ void __launch_bounds__(256) gemm_h(
    const __half* __restrict__ Ah, const __half* __restrict__ Al,
    const __half* __restrict__ Bh, const __half* __restrict__ Bl,
    const float* __restrict__ bias,
    float* __restrict__ Cf, __half* __restrict__ Chh,
    int M, int K, int N) {
    extern __shared__ char smc[];
    const unsigned smb = sh_addr(smc);
    constexpr unsigned STAGE_B = (COMP ? 4 : 2) * PLANE_B;
    const int tid = threadIdx.x, warp = tid >> 5, lane = tid & 31;
    const int bm = blockIdx.y * 128, bn = blockIdx.x * 128;
    const int wm = (warp & 3) * 32, wn = (warp >> 2) * 64;
    const int g = lane >> 2, tg = lane & 3;
    const int KT = K >> 5;

    float acc[2][8][4];
    #pragma unroll
    for (int i = 0; i < 2; i++)
        #pragma unroll
        for (int j = 0; j < 8; j++)
            #pragma unroll
            for (int k = 0; k < 4; k++) acc[i][j][k] = 0.f;

    auto load_stage = [&](int s, int kt) {
        if (kt < KT) {
            unsigned base = smb + s * STAGE_B;
            #pragma unroll
            for (int i = 0; i < 2; i++) {
                int idx = tid + i * 256;
                int r = idx >> 2, c = idx & 3;
                size_t goA = (size_t)(bm + r) * K + kt * 32 + c * 8;
                size_t goB = (size_t)(bn + r) * K + kt * 32 + c * 8;
                unsigned so = (unsigned)(r * 80 + c * 16);
                cpa16(base + so, Ah + goA);
                cpa16(base + PLANE_B + so, Bh + goB);
                if (COMP) {
                    cpa16(base + 2 * PLANE_B + so, Al + goA);
                    cpa16(base + 3 * PLANE_B + so, Bl + goB);
                }
            }
        }
        cpa_commit();
    };
    load_stage(0, 0);
    load_stage(1, 1);

    const int lrow = lane & 15;
    const int lko = (lane >> 4) * 8;

    for (int kt = 0; kt < KT; kt++) {
        if (kt < KT - 1) asm volatile("cp.async.wait_group 1;" ::: "memory");
        else             asm volatile("cp.async.wait_group 0;" ::: "memory");
        __syncthreads();
        int s = kt % 3;
        if (kt + 2 < KT) load_stage((kt + 2) % 3, kt + 2);
        unsigned aB = smb + s * STAGE_B;
        unsigned bB = aB + PLANE_B;
        #pragma unroll
        for (int ks2 = 0; ks2 < 2; ks2++) {
            int k0 = ks2 * 16;
            unsigned ah[2][4], bh[4][4];
            #pragma unroll
            for (int mt = 0; mt < 2; mt++)
                ldsm4(ah[mt], aB + (unsigned)((wm + mt * 16 + lrow) * RSTR + k0 + lko) * 2);
            #pragma unroll
            for (int nt = 0; nt < 4; nt++)
                ldsm4(bh[nt], bB + (unsigned)((wn + nt * 16 + lrow) * RSTR + k0 + lko) * 2);
            #pragma unroll
            for (int ns = 0; ns < 8; ns++) {
                int nt = ns >> 1, hf = ns & 1;
                unsigned b0 = bh[nt][hf], b1 = bh[nt][hf + 2];
                mma_f16(acc[0][ns], ah[0], b0, b1);
                mma_f16(acc[1][ns], ah[1], b0, b1);
            }
            if (COMP) {
                unsigned al[2][4], bl[4][4];
                #pragma unroll
                for (int mt = 0; mt < 2; mt++)
                    ldsm4(al[mt], aB + 2 * PLANE_B + (unsigned)((wm + mt * 16 + lrow) * RSTR + k0 + lko) * 2);
                #pragma unroll
                for (int nt = 0; nt < 4; nt++)
                    ldsm4(bl[nt], bB + 2 * PLANE_B + (unsigned)((wn + nt * 16 + lrow) * RSTR + k0 + lko) * 2);
                #pragma unroll
                for (int ns = 0; ns < 8; ns++) {
                    int nt = ns >> 1, hf = ns & 1;
                    unsigned bl0 = bl[nt][hf], bl1 = bl[nt][hf + 2];
                    unsigned bh0 = bh[nt][hf], bh1 = bh[nt][hf + 2];
                    mma_f16(acc[0][ns], ah[0], bl0, bl1);
                    mma_f16(acc[1][ns], ah[1], bl0, bl1);
                    mma_f16(acc[0][ns], al[0], bh0, bh1);
                    mma_f16(acc[1][ns], al[1], bh0, bh1);
                }
            }
        }
        __syncthreads();  // convergence barrier (load-bearing, see R6 post-mortem)
    }

    #pragma unroll
    for (int mf = 0; mf < 2; mf++) {
        int row = bm + wm + mf * 16 + g;
        #pragma unroll
        for (int nf = 0; nf < 8; nf++) {
            int col = bn + wn + nf * 8 + tg * 2;
            float b0v = bias[col], b1v = bias[col + 1];
            float v00 = acc[mf][nf][0] + b0v, v01 = acc[mf][nf][1] + b1v;
            float v10 = acc[mf][nf][2] + b0v, v11 = acc[mf][nf][3] + b1v;
            if (EPI == 1) {
                __half2 p0, p1;
                p0.x = __float2half_rn(gelu_f(v00)); p0.y = __float2half_rn(gelu_f(v01));
                p1.x = __float2half_rn(gelu_f(v10)); p1.y = __float2half_rn(gelu_f(v11));
                *(__half2*)&Chh[(size_t)row * N + col]       = p0;
                *(__half2*)&Chh[(size_t)(row + 8) * N + col] = p1;
            } else {
                *(float2*)&Cf[(size_t)row * N + col]       = make_float2(v00, v01);
                *(float2*)&Cf[(size_t)(row + 8) * N + col] = make_float2(v10, v11);
            }
        }
    }
}

// ---------------- fp16 GEMM 128x128x32, 3-stage, 4 warps (warp tile 64x64) ----------------
// Same smem layout/footprint as gemm_h<*,false>; mma:ldsm ratio 32:8 per k16.
template <int EPI>  // 0=bias fp32, 1=bias+gelu fp16
__global__ void __launch_bounds__(128) gemm_h4(
    const __half* __restrict__ Ah, const __half* __restrict__ Bh,
    const float* __restrict__ bias,
    float* __restrict__ Cf, __half* __restrict__ Chh,
    int M, int K, int N) {
    extern __shared__ char smc[];
    const unsigned smb = sh_addr(smc);
    const unsigned STAGE_B = 2 * PLANE_B;
    const int tid = threadIdx.x, warp = tid >> 5, lane = tid & 31;
    const int bm = blockIdx.y * 128, bn = blockIdx.x * 128;
    const int wm = (warp & 1) * 64, wn = (warp >> 1) * 64;
    const int g = lane >> 2, tg = lane & 3;
    const int KT = K >> 5;

    float acc[4][8][4];
    #pragma unroll
    for (int i = 0; i < 4; i++)
        #pragma unroll
        for (int j = 0; j < 8; j++)
            #pragma unroll
            for (int k = 0; k < 4; k++) acc[i][j][k] = 0.f;

    auto load_stage = [&](int s, int kt) {
        if (kt < KT) {
            unsigned base = smb + s * STAGE_B;
            #pragma unroll
            for (int i = 0; i < 4; i++) {
                int idx = tid + i * 128;
                int r = idx >> 2, c = idx & 3;
                size_t goA = (size_t)(bm + r) * K + kt * 32 + c * 8;
                size_t goB = (size_t)(bn + r) * K + kt * 32 + c * 8;
                unsigned so = (unsigned)(r * 80 + c * 16);
                cpa16(base + so, Ah + goA);
                cpa16(base + PLANE_B + so, Bh + goB);
            }
        }
        cpa_commit();
    };
    load_stage(0, 0);
    load_stage(1, 1);

    const int lrow = lane & 15;
    const int lko = (lane >> 4) * 8;

    for (int kt = 0; kt < KT; kt++) {
        if (kt < KT - 1) asm volatile("cp.async.wait_group 1;" ::: "memory");
        else             asm volatile("cp.async.wait_group 0;" ::: "memory");
        __syncthreads();
        int s = kt % 3;
        if (kt + 2 < KT) load_stage((kt + 2) % 3, kt + 2);
        unsigned aB = smb + s * STAGE_B;
        unsigned bB = aB + PLANE_B;
        #pragma unroll
        for (int ks2 = 0; ks2 < 2; ks2++) {
            int k0 = ks2 * 16;
            unsigned ah[4][4], bh[4][4];
            #pragma unroll
            for (int mt = 0; mt < 4; mt++)
                ldsm4(ah[mt], aB + (unsigned)((wm + mt * 16 + lrow) * RSTR + k0 + lko) * 2);
            #pragma unroll
            for (int nt = 0; nt < 4; nt++)
                ldsm4(bh[nt], bB + (unsigned)((wn + nt * 16 + lrow) * RSTR + k0 + lko) * 2);
            #pragma unroll
            for (int mt = 0; mt < 4; mt++)
                #pragma unroll
                for (int ns = 0; ns < 8; ns++) {
                    int nt = ns >> 1, hf = ns & 1;
                    mma_f16(acc[mt][ns], ah[mt], bh[nt][hf], bh[nt][hf + 2]);
                }
        }
        __syncthreads();  // convergence barrier
    }

    #pragma unroll
    for (int mt = 0; mt < 4; mt++) {
        int row = bm + wm + mt * 16 + g;
        #pragma unroll
        for (int nf = 0; nf < 8; nf++) {
            int col = bn + wn + nf * 8 + tg * 2;
            float b0v = bias[col], b1v = bias[col + 1];
            float v00 = acc[mt][nf][0] + b0v, v01 = acc[mt][nf][1] + b1v;
            float v10 = acc[mt][nf][2] + b0v, v11 = acc[mt][nf][3] + b1v;
            if (EPI == 1) {
                __half2 p0, p1;
                p0.x = __float2half_rn(gelu_f(v00)); p0.y = __float2half_rn(gelu_f(v01));
                p1.x = __float2half_rn(gelu_f(v10)); p1.y = __float2half_rn(gelu_f(v11));
                *(__half2*)&Chh[(size_t)row * N + col]       = p0;
                *(__half2*)&Chh[(size_t)(row + 8) * N + col] = p1;
            } else {
                *(float2*)&Cf[(size_t)row * N + col]       = make_float2(v00, v01);
                *(float2*)&Cf[(size_t)(row + 8) * N + col] = make_float2(v10, v11);
            }
        }
    }
}

// ---------------- fp16 dual-score flash attention ----------------
#define QS2 136
#define VS2 72
#define PS2 72
__global__ void __launch_bounds__(256) attn_h16(const __half* __restrict__ Qc,
                                                const __half* __restrict__ Qv,
                                                const __half* __restrict__ Kf,
                                                const __half* __restrict__ Vt,
                                                __half* __restrict__ outh) {
    extern __shared__ char smc[];
    const unsigned smb = sh_addr(smc);
    const unsigned qsb = smb;
    const unsigned ksb = qsb + 128 * QS2 * 2;
    const unsigned vsb = ksb + 2 * 64 * QS2 * 2;
    const unsigned psb = vsb + 2 * 64 * VS2 * 2;
    const int tid = threadIdx.x, warp = tid >> 5, lane = tid & 31;
    const int g = lane >> 2, tg = lane & 3;
    const int q0 = blockIdx.x * 128, h = blockIdx.y, b = blockIdx.z;
    const int bh = b * NH + h;

    const __half* qcb_ = Qc + ((size_t)(b * NQ + q0)) * DI + h * HD;
    const __half* qvb_ = Qv + ((size_t)(b * NQ + q0)) * DI + h * HD;
    #pragma unroll
    for (int i = 0; i < 8; i++) {
        int idx = tid + i * 256;
        int r = idx >> 4, c = idx & 15;
        const __half* src = (c < 8) ? (qcb_ + (size_t)r * DI + c * 8)
                                    : (qvb_ + (size_t)r * DI + (c - 8) * 8);
        cpa16(qsb + (unsigned)(r * QS2 + c * 8) * 2, src);
    }
    cpa_commit();

    const __half* kfb = Kf + (size_t)bh * NL * 128;
    const __half* vtb = Vt + (size_t)bh * 64 * NL;
    auto load_kv = [&](int s, int m0) {
        unsigned ks_ = ksb + s * (64 * QS2 * 2);
        unsigned vs_ = vsb + s * (64 * VS2 * 2);
        #pragma unroll
        for (int i = 0; i < 4; i++) {
            int idx = tid + i * 256;
            int r = idx >> 4, c = idx & 15;
            cpa16(ks_ + (unsigned)(r * QS2 + c * 8) * 2, kfb + (size_t)(m0 + r) * 128 + c * 8);
        }
        #pragma unroll
        for (int i = 0; i < 2; i++) {
            int idx = tid + i * 256;
            int r = idx >> 3, c = idx & 7;
            cpa16(vs_ + (unsigned)(r * VS2 + c * 8) * 2, vtb + (size_t)r * NL + m0 + c * 8);
        }
        cpa_commit();
    };
    load_kv(0, 0);
    load_kv(1, 64);

    float m_[2] = {-1e30f, -1e30f}, l_[2] = {0.f, 0.f};
    float o[8][4];
    #pragma unroll
    for (int i = 0; i < 8; i++)
        #pragma unroll
        for (int j = 0; j < 4; j++) o[i][j] = 0.f;

    const int wrow = warp * 16;
    const int lrow = lane & 15;
    const int lko = (lane >> 4) * 8;
    const int NIT = NL / 64;

    for (int it = 0; it < NIT; it++) {
        if (it < NIT - 1) asm volatile("cp.async.wait_group 1;" ::: "memory");
        else              asm volatile("cp.async.wait_group 0;" ::: "memory");
        __syncthreads();
        int s = it & 1;
        unsigned ksp = ksb + s * (64 * QS2 * 2);
        unsigned vsp = vsb + s * (64 * VS2 * 2);

        float sacc[8][4];
        #pragma unroll
        for (int i = 0; i < 8; i++)
            #pragma unroll
            for (int j = 0; j < 4; j++) sacc[i][j] = 0.f;
        #pragma unroll
        for (int kc2 = 0; kc2 < 8; kc2++) {
            int k0 = kc2 * 16;
            unsigned a[4], bh4[4][4];
            ldsm4(a, qsb + (unsigned)((wrow + lrow) * QS2 + k0 + lko) * 2);
            #pragma unroll
            for (int nt = 0; nt < 4; nt++)
                ldsm4(bh4[nt], ksp + (unsigned)((nt * 16 + lrow) * QS2 + k0 + lko) * 2);
            #pragma unroll
            for (int ns = 0; ns < 8; ns++) {
                int nt = ns >> 1, hf = ns & 1;
                mma_f16(sacc[ns], a, bh4[nt][hf], bh4[nt][hf + 2]);
            }
        }

        #pragma unroll
        for (int rw = 0; rw < 2; rw++) {
            float mx = -1e30f;
            #pragma unroll
            for (int nf = 0; nf < 8; nf++)
                mx = fmaxf(mx, fmaxf(sacc[nf][2 * rw], sacc[nf][2 * rw + 1]));
            mx = fmaxf(mx, __shfl_xor_sync(0xffffffffu, mx, 1));
            mx = fmaxf(mx, __shfl_xor_sync(0xffffffffu, mx, 2));
            float mn = fmaxf(m_[rw], mx);
            float corr = __expf(m_[rw] - mn);
            m_[rw] = mn;
            float sum = 0.f;
            int prow = wrow + rw * 8 + g;
            #pragma unroll
            for (int nf = 0; nf < 8; nf++) {
                float p0 = __expf(sacc[nf][2 * rw] - mn);
                float p1 = __expf(sacc[nf][2 * rw + 1] - mn);
                sum += p0 + p1;
                __half2 ph; ph.x = __float2half_rn(p0); ph.y = __float2half_rn(p1);
                unsigned pa = psb + (unsigned)(prow * PS2 + nf * 8 + tg * 2) * 2;
                asm volatile("st.shared.b32 [%0], %1;" :: "r"(pa), "r"(*(unsigned*)&ph));
            }
            sum += __shfl_xor_sync(0xffffffffu, sum, 1);
            sum += __shfl_xor_sync(0xffffffffu, sum, 2);
            l_[rw] = l_[rw] * corr + sum;
            #pragma unroll
            for (int nf = 0; nf < 8; nf++) {
                o[nf][2 * rw]     *= corr;
                o[nf][2 * rw + 1] *= corr;
            }
        }
        __syncwarp();

        #pragma unroll
        for (int kc2 = 0; kc2 < 4; kc2++) {
            int k0 = kc2 * 16;
            unsigned a[4], bv[4][4];
            ldsm4(a, psb + (unsigned)((wrow + lrow) * PS2 + k0 + lko) * 2);
            #pragma unroll
            for (int nt = 0; nt < 4; nt++)
                ldsm4(bv[nt], vsp + (unsigned)((nt * 16 + lrow) * VS2 + k0 + lko) * 2);
            #pragma unroll
            for (int ns = 0; ns < 8; ns++) {
                int nt = ns >> 1, hf = ns & 1;
                mma_f16(o[ns], a, bv[nt][hf], bv[nt][hf + 2]);
            }
        }
        __syncthreads();
        if (it + 2 < NIT) load_kv(s, (it + 2) * 64);
    }

    #pragma unroll
    for (int rw = 0; rw < 2; rw++) {
        float inv = 1.f / l_[rw];
        int row = b * NQ + q0 + wrow + rw * 8 + g;
        #pragma unroll
        for (int nf = 0; nf < 8; nf++) {
            int col = h * HD + nf * 8 + tg * 2;
            __half2 hv;
            hv.x = __float2half_rn(o[nf][2 * rw] * inv);
            hv.y = __float2half_rn(o[nf][2 * rw + 1] * inv);
            *(__half2*)&outh[(size_t)row * DI + col] = hv;
        }
    }
}

// ---------------- host launcher ----------------
static void fill_ws(WsArgs& wa, const float** Ws, __half* wth, __half* wtl,
                    const int* Ks, const int* Ns, const int* offs, int n, int& total) {
    int acc0 = 0;
    for (int i = 0; i < n; i++) {
        wa.W[i] = Ws[i]; wa.th[i] = wth + offs[i]; wa.tl[i] = wtl + offs[i];
        wa.K[i] = Ks[i]; wa.N[i] = Ns[i];
        wa.start[i] = acc0;
        acc0 += (Ks[i] / 32) * (Ns[i] / 32);
    }
    for (int i = n; i < 9; i++) wa.start[i] = 0x7FFFFFFF;
    total = acc0;
}

extern "C" void kernel_launch(void* const* d_in, const int* in_sizes, int n_in,
                              void* d_out, int out_size) {
    const float* coords = (const float*)d_in[0];
    const float* values = (const float*)d_in[1];
    const float* Lv     = (const float*)d_in[2];
    const float* Lc     = (const float*)d_in[3];
    const float* lam    = (const float*)d_in[4];
    const float* lvn_g  = (const float*)d_in[5];
    const float* lvn_b  = (const float*)d_in[6];
    const float* lcn_g  = (const float*)d_in[7];
    const float* lcn_b  = (const float*)d_in[8];
    const float* ck_w   = (const float*)d_in[9];
    const float* ck_b   = (const float*)d_in[10];
    const float* ck_g   = (const float*)d_in[11];
    const float* cq_w   = (const float*)d_in[12];
    const float* cq_b   = (const float*)d_in[13];
    const float* cq_g   = (const float*)d_in[14];
    const float* vq_w   = (const float*)d_in[15];
    const float* vq_b   = (const float*)d_in[16];
    const float* vq_g   = (const float*)d_in[17];
    const float* vk_w   = (const float*)d_in[18];
    const float* vk_b   = (const float*)d_in[19];
    const float* op_w   = (const float*)d_in[20];
    const float* op_b   = (const float*)d_in[21];
    const float* oln_g  = (const float*)d_in[22];
    const float* oln_b  = (const float*)d_in[23];
    const float* m1_w   = (const float*)d_in[24];
    const float* m1_b   = (const float*)d_in[25];
    const float* m2_w   = (const float*)d_in[26];
    const float* m2_b   = (const float*)d_in[27];
    const float* m3_w   = (const float*)d_in[28];
    const float* m3_b   = (const float*)d_in[29];
    float* out = (float*)d_out;

    float *vkb, *kcb, *qvb, *qcb, *yb;
    cudaGetSymbolAddress((void**)&vkb, g_vk);
    cudaGetSymbolAddress((void**)&kcb, g_kc);
    cudaGetSymbolAddress((void**)&qvb, g_qv);
    cudaGetSymbolAddress((void**)&qcb, g_qc);
    cudaGetSymbolAddress((void**)&yb,  g_y);
    __half *sLvh, *sLvl, *sLch, *sLcl, *valh, *vall, *crdh, *crdl;
    __half *atth, *ybsh, *ybsl, *h1h, *h2h, *wth, *wtl;
    __half *qvh, *qch, *kf, *vt;
    cudaGetSymbolAddress((void**)&sLvh, g_sLv_h); cudaGetSymbolAddress((void**)&sLvl, g_sLv_l);
    cudaGetSymbolAddress((void**)&sLch, g_sLc_h); cudaGetSymbolAddress((void**)&sLcl, g_sLc_l);
    cudaGetSymbolAddress((void**)&valh, g_val_h); cudaGetSymbolAddress((void**)&vall, g_val_l);
    cudaGetSymbolAddress((void**)&crdh, g_crd_h); cudaGetSymbolAddress((void**)&crdl, g_crd_l);
    cudaGetSymbolAddress((void**)&atth, g_att_h);
    cudaGetSymbolAddress((void**)&ybsh, g_ybs_h); cudaGetSymbolAddress((void**)&ybsl, g_ybs_l);
    cudaGetSymbolAddress((void**)&h1h,  g_h1_h);
    cudaGetSymbolAddress((void**)&h2h,  g_h2_h);
    cudaGetSymbolAddress((void**)&wth,  g_wth);   cudaGetSymbolAddress((void**)&wtl,  g_wtl);
    cudaGetSymbolAddress((void**)&qvh,  g_qvh);   cudaGetSymbolAddress((void**)&qch,  g_qch);
    cudaGetSymbolAddress((void**)&kf,   g_kf);    cudaGetSymbolAddress((void**)&vt,   g_vt);

    const int BNL = BATCH * NL;
    const int BNQ = BATCH * NQ;
    const int GSMC = 3 * 4 * PLANE_B;  // 122880
    const int GSM1 = 3 * 2 * PLANE_B;  // 61440
    const int ATTN_SMEM = 128 * QS2 * 2 + 2 * 64 * QS2 * 2 + 2 * 64 * VS2 * 2 + 128 * PS2 * 2;
    cudaFuncSetAttribute((const void*)gemm_h<0, true>,  cudaFuncAttributeMaxDynamicSharedMemorySize, GSMC);
    cudaFuncSetAttribute((const void*)gemm_h<0, false>, cudaFuncAttributeMaxDynamicSharedMemorySize, GSM1);
    cudaFuncSetAttribute((const void*)gemm_h4<0>,       cudaFuncAttributeMaxDynamicSharedMemorySize, GSM1);
    cudaFuncSetAttribute((const void*)gemm_h4<1>,       cudaFuncAttributeMaxDynamicSharedMemorySize, GSM1);
    cudaFuncSetAttribute(attn_h16, cudaFuncAttributeMaxDynamicSharedMemorySize, ATTN_SMEM);

    // side stream + events (host-side only)
    cudaStream_t s1;
    cudaStreamCreateWithFlags(&s1, cudaStreamNonBlocking);
    cudaEvent_t eF, eW, eK;
    cudaEventCreateWithFlags(&eF, cudaEventDisableTiming);
    cudaEventCreateWithFlags(&eW, cudaEventDisableTiming);
    cudaEventCreateWithFlags(&eK, cudaEventDisableTiming);

    // fork: latent/K branch starts immediately
    cudaEventRecord(eF, 0);
    cudaStreamWaitEvent(s1, eF, 0);
    layernorm_split<<<BNL, 256, 0, s1>>>(Lv, lvn_g, lvn_b, sLvh, sLvl, DV, 1e-5f);
    layernorm_split<<<BNL, 128, 0, s1>>>(Lc, lcn_g, lcn_b, sLch, sLcl, DC, 1e-5f);

    // weight split, PHASE 1: projection weights only (unblocks both GEMM branches early)
    {
        WsArgs wa; int tot;
        const float* Ws[4] = {ck_w, cq_w, vq_w, vk_w};
        int Ks[4] = {DC, DC, DV, DV};
        int Ns[4] = {DI, DI, DI, 2 * DI};
        int offs[4] = {OFF_CKW, OFF_CQW, OFF_VQW, OFF_VKW};
        fill_ws(wa, Ws, wth, wtl, Ks, Ns, offs, 4, tot);
        wtsplit_all<<<tot, dim3(32, 8)>>>(wa);
    }
    cudaEventRecord(eW, 0);

    // weight split, PHASE 2: MLP-path weights (overlaps with projection GEMMs;
    // same main stream -> ordered before op/m1/m2/m3 use them)
    {
        WsArgs wa; int tot;
        const float* Ws[4] = {op_w, m1_w, m2_w, m3_w};
        int Ks[4] = {DI, DV, DF, DF};
        int Ns[4] = {DV, DF, DF, DV};
        int offs[4] = {OFF_OPW, OFF_M1W, OFF_M2W, OFF_M3W};
        fill_ws(wa, Ws, wth, wtl, Ks, Ns, offs, 4, tot);
        wtsplit_all<<<tot, dim3(32, 8)>>>(wa);
    }

    // latent/K branch on s1 (vk single-pass; ck compensated)
    cudaStreamWaitEvent(s1, eW, 0);
    gemm_h<0, false><<<dim3(8, 32), 256, GSM1, s1>>>(sLvh, (__half*)0, wth + OFF_VKW, (__half*)0,
                                                     vk_b, vkb, (__half*)0, BNL, DV, 2 * DI);
    gemm_h<0, true><<<dim3(4, 32), 256, GSMC, s1>>>(sLch, sLcl, wth + OFF_CKW, wtl + OFF_CKW,
                                                    ck_b, kcb, (__half*)0, BNL, DC, DI);
    rmsnorm_kernel<<<BNL, 256, 0, s1>>>(kcb, ck_g, DI, 1e-6f, 1.0f);
    kcomb_kernel<<<dim3(NL, BATCH), 256, 0, s1>>>(kcb, vkb, lam, kf);
    vtrans_kernel<<<dim3(NL/32, 2, BATCH*NH), dim3(32, 8), 0, s1>>>(vkb, vt);
    cudaEventRecord(eK, s1);

    // q branch on main stream (vq single-pass; cq compensated)
    split_copy_h<<<BNQ * DV / 4 / 256, 256>>>(values, valh, vall, BNQ * DV / 4);
    split_copy_h<<<BNQ * DC / 4 / 256, 256>>>(coords, crdh, crdl, BNQ * DC / 4);
    gemm_h<0, false><<<dim3(4, 128), 256, GSM1>>>(valh, (__half*)0, wth + OFF_VQW, (__half*)0,
                                                  vq_b, qvb, (__half*)0, BNQ, DV, DI);
    gemm_h<0, true><<<dim3(4, 128), 256, GSMC>>>(crdh, crdl, wth + OFF_CQW, wtl + OFF_CQW,
                                                 cq_b, qcb, (__half*)0, BNQ, DC, DI);
    rmsnorm_h<<<BNQ, 256>>>(qvb, vq_g, qvh, DI, 1e-6f, 0.125f);
    rmsnorm_h<<<BNQ, 256>>>(qcb, cq_g, qch, DI, 1e-6f, 0.125f);

    // join, then attention + tail
    cudaStreamWaitEvent(0, eK, 0);
    attn_h16<<<dim3(NQ/128, NH, BATCH), 256, ATTN_SMEM>>>(qch, qvh, kf, vt, atth);

    gemm_h<0, false><<<dim3(4, 128), 256, GSM1>>>(atth, (__half*)0, wth + OFF_OPW, (__half*)0,
                                                  op_b, yb, (__half*)0, BNQ, DI, DV);
    layernorm_split<<<BNQ, 256>>>(yb, oln_g, oln_b, ybsh, ybsl, DV, 1e-5f);
    gemm_h4<1><<<dim3(16, 128), 128, GSM1>>>(ybsh, wth + OFF_M1W, m1_b,
                                             (float*)0, h1h, BNQ, DV, DF);
    gemm_h4<1><<<dim3(16, 128), 128, GSM1>>>(h1h, wth + OFF_M2W, m2_b,
                                             (float*)0, h2h, BNQ, DF, DF);
    gemm_h4<0><<<dim3(4, 128), 128, GSM1>>>(h2h, wth + OFF_M3W, m3_b,
                                            out, (__half*)0, BNQ, DF, DV);
}

// round 13
// speedup vs baseline: 1.0051x; 1.0051x over previous
#include <cuda_runtime.h>
#include <cuda_fp16.h>
#include <math.h>
#include <cstdint>

#define BATCH 4
#define NQ 4096
#define NL 1024
#define DV 512
#define DC 128
#define DI 512
#define DF 2048
#define NH 8
#define HD 64

// ---------------- device scratch ----------------
__device__ float g_vk [BATCH * NL * (2 * DI)];
__device__ float g_kc [BATCH * NL * DI];
__device__ float g_qv [BATCH * NQ * DI];
__device__ float g_qc [BATCH * NQ * DI];
__device__ float g_y  [BATCH * NQ * DV];
__device__ __align__(16) __half g_qvh[BATCH * NQ * DI], g_qch[BATCH * NQ * DI];
__device__ __align__(16) __half g_kf [BATCH * NH * NL * 128];   // [bh][j][kc|lam*kv]
__device__ __align__(16) __half g_vt [BATCH * NH * 64 * NL];    // [bh][d][j]
__device__ __align__(16) __half g_sLv_h[BATCH * NL * DV], g_sLv_l[BATCH * NL * DV];
__device__ __align__(16) __half g_sLc_h[BATCH * NL * DC], g_sLc_l[BATCH * NL * DC];
__device__ __align__(16) __half g_val_h[BATCH * NQ * DV], g_val_l[BATCH * NQ * DV];
__device__ __align__(16) __half g_crd_h[BATCH * NQ * DC], g_crd_l[BATCH * NQ * DC];
__device__ __align__(16) __half g_att_h[BATCH * NQ * DI];
__device__ __align__(16) __half g_ybs_h[BATCH * NQ * DV], g_ybs_l[BATCH * NQ * DV];
__device__ __align__(16) __half g_h1_h[BATCH * NQ * DF];
__device__ __align__(16) __half g_h2_h[BATCH * NQ * DF];
__device__ __align__(16) __half g_wth[7471104], g_wtl[7471104];

#define OFF_CKW 0
#define OFF_CQW 65536
#define OFF_VQW 131072
#define OFF_VKW 393216
#define OFF_OPW 917504
#define OFF_M1W 1179648
#define OFF_M2W 2228224
#define OFF_M3W 6422528

// ---------------- helpers ----------------
__device__ __forceinline__ float gelu_f(float x) {
    float x3 = x * x * x;
    return 0.5f * x * (1.0f + tanhf(0.7978845608028654f * (x + 0.044715f * x3)));
}
__device__ __forceinline__ void split2h(float x, __half& h, __half& l) {
    h = __float2half_rn(x);
    l = __float2half_rn(x - __half2float(h));
}
__device__ __forceinline__ void mma_f16(float* c, const unsigned* a, unsigned b0, unsigned b1) {
    asm volatile(
        "mma.sync.aligned.m16n8k16.row.col.f32.f16.f16.f32 "
        "{%0,%1,%2,%3},{%4,%5,%6,%7},{%8,%9},{%0,%1,%2,%3};"
        : "+f"(c[0]), "+f"(c[1]), "+f"(c[2]), "+f"(c[3])
        : "r"(a[0]), "r"(a[1]), "r"(a[2]), "r"(a[3]), "r"(b0), "r"(b1));
}
__device__ __forceinline__ void ldsm4(unsigned* r, unsigned addr) {
    asm volatile("ldmatrix.sync.aligned.m8n8.x4.shared.b16 {%0,%1,%2,%3}, [%4];"
        : "=r"(r[0]), "=r"(r[1]), "=r"(r[2]), "=r"(r[3]) : "r"(addr));
}
__device__ __forceinline__ void cpa16(unsigned dst, const void* src) {
    asm volatile("cp.async.cg.shared.global [%0], [%1], 16;" :: "r"(dst), "l"(src));
}
__device__ __forceinline__ void cpa_commit() { asm volatile("cp.async.commit_group;"); }
__device__ __forceinline__ unsigned sh_addr(const void* p) {
    return (unsigned)__cvta_generic_to_shared(p);
}

// ---------------- producers ----------------
__global__ void split_copy_h(const float* __restrict__ x, __half* __restrict__ h,
                             __half* __restrict__ l, int n4) {
    int i = blockIdx.x * blockDim.x + threadIdx.x;
    if (i < n4) {
        float4 v = ((const float4*)x)[i];
        int b = i * 4;
        __half h0, l0; split2h(v.x, h0, l0); h[b] = h0; l[b] = l0;
        split2h(v.y, h0, l0); h[b+1] = h0; l[b+1] = l0;
        split2h(v.z, h0, l0); h[b+2] = h0; l[b+2] = l0;
        split2h(v.w, h0, l0); h[b+3] = h0; l[b+3] = l0;
    }
}

// batched weight split+transpose (subset of up to 8 layers per launch)
struct WsArgs {
    const float* W[8];
    __half* th[8];
    __half* tl[8];
    int K[8], N[8];
    int start[9];
};
__global__ void wtsplit_all(WsArgs a) {
    __shared__ float t[32][33];
    int bid = blockIdx.x;
    int l = 0;
    #pragma unroll
    for (int i = 1; i < 8; i++) if (bid >= a.start[i]) l = i;
    int tidx = bid - a.start[l];
    int K = a.K[l], N = a.N[l];
    int ntn = N >> 5;
    int k0 = (tidx / ntn) << 5;
    int n0 = (tidx % ntn) << 5;
    const float* W = a.W[l];
    __half* th = a.th[l];
    __half* tl = a.tl[l];
    int tx = threadIdx.x, ty = threadIdx.y;
    for (int dy = ty; dy < 32; dy += 8)
        t[dy][tx] = W[(size_t)(k0 + dy) * N + n0 + tx];
    __syncthreads();
    for (int rr = ty; rr < 32; rr += 8) {
        __half h, lo; split2h(t[tx][rr], h, lo);
        th[(size_t)(n0 + rr) * K + k0 + tx] = h;
        tl[(size_t)(n0 + rr) * K + k0 + tx] = lo;
    }
}

__global__ void layernorm_split(const float* __restrict__ x, const float* __restrict__ g,
                                const float* __restrict__ b, __half* __restrict__ yh,
                                __half* __restrict__ yl, int D, float eps) {
    int row = blockIdx.x;
    const float* xr = x + (size_t)row * D;
    float s = 0.f, ss = 0.f;
    for (int i = threadIdx.x; i < D; i += blockDim.x) { float v = xr[i]; s += v; ss += v * v; }
    __shared__ float rs[32], rss[32];
    #pragma unroll
    for (int off = 16; off; off >>= 1) {
        s  += __shfl_xor_sync(0xffffffffu, s,  off);
        ss += __shfl_xor_sync(0xffffffffu, ss, off);
    }
    int w = threadIdx.x >> 5, l = threadIdx.x & 31;
    if (l == 0) { rs[w] = s; rss[w] = ss; }
    __syncthreads();
    int nw = blockDim.x >> 5;
    if (threadIdx.x < 32) {
        s  = (l < nw) ? rs[l]  : 0.f;
        ss = (l < nw) ? rss[l] : 0.f;
        #pragma unroll
        for (int off = 16; off; off >>= 1) {
            s  += __shfl_xor_sync(0xffffffffu, s,  off);
            ss += __shfl_xor_sync(0xffffffffu, ss, off);
        }
        if (l == 0) { rs[0] = s; rss[0] = ss; }
    }
    __syncthreads();
    float mean = rs[0] / (float)D;
    float inv  = rsqrtf(rss[0] / (float)D - mean * mean + eps);
    for (int i = threadIdx.x; i < D; i += blockDim.x) {
        __half h, lo; split2h((xr[i] - mean) * inv * g[i] + b[i], h, lo);
        yh[(size_t)row * D + i] = h; yl[(size_t)row * D + i] = lo;
    }
}

__global__ void rmsnorm_kernel(float* __restrict__ x, const float* __restrict__ g,
                               int D, float eps, float scale) {
    int row = blockIdx.x;
    float* xr = x + (size_t)row * D;
    float ss = 0.f;
    for (int i = threadIdx.x; i < D; i += blockDim.x) { float v = xr[i]; ss += v * v; }
    __shared__ float rss[32];
    #pragma unroll
    for (int off = 16; off; off >>= 1) ss += __shfl_xor_sync(0xffffffffu, ss, off);
    int w = threadIdx.x >> 5, l = threadIdx.x & 31;
    if (l == 0) rss[w] = ss;
    __syncthreads();
    int nw = blockDim.x >> 5;
    if (threadIdx.x < 32) {
        ss = (l < nw) ? rss[l] : 0.f;
        #pragma unroll
        for (int off = 16; off; off >>= 1) ss += __shfl_xor_sync(0xffffffffu, ss, off);
        if (l == 0) rss[0] = ss;
    }
    __syncthreads();
    float inv = rsqrtf(rss[0] / (float)D + eps) * scale;
    for (int i = threadIdx.x; i < D; i += blockDim.x)
        xr[i] = xr[i] * inv * g[i];
}

__global__ void rmsnorm_h(const float* __restrict__ x, const float* __restrict__ g,
                          __half* __restrict__ y, int D, float eps, float scale) {
    int row = blockIdx.x;
    const float* xr = x + (size_t)row * D;
    float ss = 0.f;
    for (int i = threadIdx.x; i < D; i += blockDim.x) { float v = xr[i]; ss += v * v; }
    __shared__ float rss[32];
    #pragma unroll
    for (int off = 16; off; off >>= 1) ss += __shfl_xor_sync(0xffffffffu, ss, off);
    int w = threadIdx.x >> 5, l = threadIdx.x & 31;
    if (l == 0) rss[w] = ss;
    __syncthreads();
    int nw = blockDim.x >> 5;
    if (threadIdx.x < 32) {
        ss = (l < nw) ? rss[l] : 0.f;
        #pragma unroll
        for (int off = 16; off; off >>= 1) ss += __shfl_xor_sync(0xffffffffu, ss, off);
        if (l == 0) rss[0] = ss;
    }
    __syncthreads();
    float inv = rsqrtf(rss[0] / (float)D + eps) * scale;
    for (int i = threadIdx.x; i < D; i += blockDim.x)
        y[(size_t)row * D + i] = __float2half_rn(xr[i] * inv * g[i]);
}

__global__ void kcomb_kernel(const float* __restrict__ kc, const float* __restrict__ vk,
                             const float* __restrict__ lamp, __half* __restrict__ kf) {
    int j = blockIdx.x, b = blockIdx.y;
    int tid = threadIdx.x;
    float lam = lamp[0];
    int e = tid * 4;
    int h = e >> 7, dd = e & 127;
    float4 v;
    if (dd < 64)
        v = *(const float4*)&kc[((size_t)(b * NL + j)) * DI + h * 64 + dd];
    else {
        v = *(const float4*)&vk[((size_t)(b * NL + j)) * (2 * DI) + DI + h * 64 + (dd - 64)];
        v.x *= lam; v.y *= lam; v.z *= lam; v.w *= lam;
    }
    __half* dst = kf + ((size_t)((b * NH + h) * NL + j)) * 128 + dd;
    dst[0] = __float2half_rn(v.x); dst[1] = __float2half_rn(v.y);
    dst[2] = __float2half_rn(v.z); dst[3] = __float2half_rn(v.w);
}

__global__ void vtrans_kernel(const float* __restrict__ vk, __half* __restrict__ vt) {
    __shared__ float t[32][33];
    int bh = blockIdx.z; int b = bh >> 3; int h = bh & 7;
    int j0 = blockIdx.x * 32, d0 = blockIdx.y * 32;
    int tx = threadIdx.x, ty = threadIdx.y;
    const float* s = vk + ((size_t)(b * NL + j0)) * (2 * DI) + h * HD + d0;
    for (int dy = ty; dy < 32; dy += 8)
        t[dy][tx] = s[(size_t)dy * (2 * DI) + tx];
    __syncthreads();
    for (int dy = ty; dy < 32; dy += 8)
        vt[((size_t)(bh * 64 + d0 + dy)) * NL + j0 + tx] = __float2half_rn(t[tx][dy]);
}

// ---------------- fp16 GEMM 128x128x32, 3-stage, 8 warps (warp tile 32x64) ----------------
#define RSTR 40
#define PLANE_B (128 * RSTR * 2)  // 10240
template <int EPI, bool COMP>    // EPI: 0=bias fp32, 1=bias+gelu fp16
__global__ void __launch_bounds__(256) gemm_h(
    const __half* __restrict__ Ah, const __half* __restrict__ Al,
    const __half* __restrict__ Bh, const __half* __restrict__ Bl,
    const float* __restrict__ bias,
    float* __restrict__ Cf, __half* __restrict__ Chh,
    int M, int K, int N) {
    extern __shared__ char smc[];
    const unsigned smb = sh_addr(smc);
    constexpr unsigned STAGE_B = (COMP ? 4 : 2) * PLANE_B;
    const int tid = threadIdx.x, warp = tid >> 5, lane = tid & 31;
    const int bm = blockIdx.y * 128, bn = blockIdx.x * 128;
    const int wm = (warp & 3) * 32, wn = (warp >> 2) * 64;
    const int g = lane >> 2, tg = lane & 3;
    const int KT = K >> 5;

    float acc[2][8][4];
    #pragma unroll
    for (int i = 0; i < 2; i++)
        #pragma unroll
        for (int j = 0; j < 8; j++)
            #pragma unroll
            for (int k = 0; k < 4; k++) acc[i][j][k] = 0.f;

    auto load_stage = [&](int s, int kt) {
        if (kt < KT) {
            unsigned base = smb + s * STAGE_B;
            #pragma unroll
            for (int i = 0; i < 2; i++) {
                int idx = tid + i * 256;
                int r = idx >> 2, c = idx & 3;
                size_t goA = (size_t)(bm + r) * K + kt * 32 + c * 8;
                size_t goB = (size_t)(bn + r) * K + kt * 32 + c * 8;
                unsigned so = (unsigned)(r * 80 + c * 16);
                cpa16(base + so, Ah + goA);
                cpa16(base + PLANE_B + so, Bh + goB);
                if (COMP) {
                    cpa16(base + 2 * PLANE_B + so, Al + goA);
                    cpa16(base + 3 * PLANE_B + so, Bl + goB);
                }
            }
        }
        cpa_commit();
    };
    load_stage(0, 0);
    load_stage(1, 1);

    const int lrow = lane & 15;
    const int lko = (lane >> 4) * 8;

    for (int kt = 0; kt < KT; kt++) {
        if (kt < KT - 1) asm volatile("cp.async.wait_group 1;" ::: "memory");
        else             asm volatile("cp.async.wait_group 0;" ::: "memory");
        __syncthreads();
        int s = kt % 3;
        if (kt + 2 < KT) load_stage((kt + 2) % 3, kt + 2);
        unsigned aB = smb + s * STAGE_B;
        unsigned bB = aB + PLANE_B;
        #pragma unroll
        for (int ks2 = 0; ks2 < 2; ks2++) {
            int k0 = ks2 * 16;
            unsigned ah[2][4], bh[4][4];
            #pragma unroll
            for (int mt = 0; mt < 2; mt++)
                ldsm4(ah[mt], aB + (unsigned)((wm + mt * 16 + lrow) * RSTR + k0 + lko) * 2);
            #pragma unroll
            for (int nt = 0; nt < 4; nt++)
                ldsm4(bh[nt], bB + (unsigned)((wn + nt * 16 + lrow) * RSTR + k0 + lko) * 2);
            #pragma unroll
            for (int ns = 0; ns < 8; ns++) {
                int nt = ns >> 1, hf = ns & 1;
                unsigned b0 = bh[nt][hf], b1 = bh[nt][hf + 2];
                mma_f16(acc[0][ns], ah[0], b0, b1);
                mma_f16(acc[1][ns], ah[1], b0, b1);
            }
            if (COMP) {
                unsigned al[2][4], bl[4][4];
                #pragma unroll
                for (int mt = 0; mt < 2; mt++)
                    ldsm4(al[mt], aB + 2 * PLANE_B + (unsigned)((wm + mt * 16 + lrow) * RSTR + k0 + lko) * 2);
                #pragma unroll
                for (int nt = 0; nt < 4; nt++)
                    ldsm4(bl[nt], bB + 2 * PLANE_B + (unsigned)((wn + nt * 16 + lrow) * RSTR + k0 + lko) * 2);
                #pragma unroll
                for (int ns = 0; ns < 8; ns++) {
                    int nt = ns >> 1, hf = ns & 1;
                    unsigned bl0 = bl[nt][hf], bl1 = bl[nt][hf + 2];
                    unsigned bh0 = bh[nt][hf], bh1 = bh[nt][hf + 2];
                    mma_f16(acc[0][ns], ah[0], bl0, bl1);
                    mma_f16(acc[1][ns], ah[1], bl0, bl1);
                    mma_f16(acc[0][ns], al[0], bh0, bh1);
                    mma_f16(acc[1][ns], al[1], bh0, bh1);
                }
            }
        }
        __syncthreads();  // convergence barrier (load-bearing, see R6 post-mortem)
    }

    #pragma unroll
    for (int mf = 0; mf < 2; mf++) {
        int row = bm + wm + mf * 16 + g;
        #pragma unroll
        for (int nf = 0; nf < 8; nf++) {
            int col = bn + wn + nf * 8 + tg * 2;
            float b0v = bias[col], b1v = bias[col + 1];
            float v00 = acc[mf][nf][0] + b0v, v01 = acc[mf][nf][1] + b1v;
            float v10 = acc[mf][nf][2] + b0v, v11 = acc[mf][nf][3] + b1v;
            if (EPI == 1) {
                __half2 p0, p1;
                p0.x = __float2half_rn(gelu_f(v00)); p0.y = __float2half_rn(gelu_f(v01));
                p1.x = __float2half_rn(gelu_f(v10)); p1.y = __float2half_rn(gelu_f(v11));
                *(__half2*)&Chh[(size_t)row * N + col]       = p0;
                *(__half2*)&Chh[(size_t)(row + 8) * N + col] = p1;
            } else {
                *(float2*)&Cf[(size_t)row * N + col]       = make_float2(v00, v01);
                *(float2*)&Cf[(size_t)(row + 8) * N + col] = make_float2(v10, v11);
            }
        }
    }
}

// ---------------- fp16 dual-score flash attention ----------------
#define QS2 136
#define VS2 72
#define PS2 72
__global__ void __launch_bounds__(256) attn_h16(const __half* __restrict__ Qc,
                                                const __half* __restrict__ Qv,
                                                const __half* __restrict__ Kf,
                                                const __half* __restrict__ Vt,
                                                __half* __restrict__ outh) {
    extern __shared__ char smc[];
    const unsigned smb = sh_addr(smc);
    const unsigned qsb = smb;
    const unsigned ksb = qsb + 128 * QS2 * 2;
    const unsigned vsb = ksb + 2 * 64 * QS2 * 2;
    const unsigned psb = vsb + 2 * 64 * VS2 * 2;
    const int tid = threadIdx.x, warp = tid >> 5, lane = tid & 31;
    const int g = lane >> 2, tg = lane & 3;
    const int q0 = blockIdx.x * 128, h = blockIdx.y, b = blockIdx.z;
    const int bh = b * NH + h;

    const __half* qcb_ = Qc + ((size_t)(b * NQ + q0)) * DI + h * HD;
    const __half* qvb_ = Qv + ((size_t)(b * NQ + q0)) * DI + h * HD;
    #pragma unroll
    for (int i = 0; i < 8; i++) {
        int idx = tid + i * 256;
        int r = idx >> 4, c = idx & 15;
        const __half* src = (c < 8) ? (qcb_ + (size_t)r * DI + c * 8)
                                    : (qvb_ + (size_t)r * DI + (c - 8) * 8);
        cpa16(qsb + (unsigned)(r * QS2 + c * 8) * 2, src);
    }
    cpa_commit();

    const __half* kfb = Kf + (size_t)bh * NL * 128;
    const __half* vtb = Vt + (size_t)bh * 64 * NL;
    auto load_kv = [&](int s, int m0) {
        unsigned ks_ = ksb + s * (64 * QS2 * 2);
        unsigned vs_ = vsb + s * (64 * VS2 * 2);
        #pragma unroll
        for (int i = 0; i < 4; i++) {
            int idx = tid + i * 256;
            int r = idx >> 4, c = idx & 15;
            cpa16(ks_ + (unsigned)(r * QS2 + c * 8) * 2, kfb + (size_t)(m0 + r) * 128 + c * 8);
        }
        #pragma unroll
        for (int i = 0; i < 2; i++) {
            int idx = tid + i * 256;
            int r = idx >> 3, c = idx & 7;
            cpa16(vs_ + (unsigned)(r * VS2 + c * 8) * 2, vtb + (size_t)r * NL + m0 + c * 8);
        }
        cpa_commit();
    };
    load_kv(0, 0);
    load_kv(1, 64);

    float m_[2] = {-1e30f, -1e30f}, l_[2] = {0.f, 0.f};
    float o[8][4];
    #pragma unroll
    for (int i = 0; i < 8; i++)
        #pragma unroll
        for (int j = 0; j < 4; j++) o[i][j] = 0.f;

    const int wrow = warp * 16;
    const int lrow = lane & 15;
    const int lko = (lane >> 4) * 8;
    const int NIT = NL / 64;

    for (int it = 0; it < NIT; it++) {
        if (it < NIT - 1) asm volatile("cp.async.wait_group 1;" ::: "memory");
        else              asm volatile("cp.async.wait_group 0;" ::: "memory");
        __syncthreads();
        int s = it & 1;
        unsigned ksp = ksb + s * (64 * QS2 * 2);
        unsigned vsp = vsb + s * (64 * VS2 * 2);

        float sacc[8][4];
        #pragma unroll
        for (int i = 0; i < 8; i++)
            #pragma unroll
            for (int j = 0; j < 4; j++) sacc[i][j] = 0.f;
        #pragma unroll
        for (int kc2 = 0; kc2 < 8; kc2++) {
            int k0 = kc2 * 16;
            unsigned a[4], bh4[4][4];
            ldsm4(a, qsb + (unsigned)((wrow + lrow) * QS2 + k0 + lko) * 2);
            #pragma unroll
            for (int nt = 0; nt < 4; nt++)
                ldsm4(bh4[nt], ksp + (unsigned)((nt * 16 + lrow) * QS2 + k0 + lko) * 2);
            #pragma unroll
            for (int ns = 0; ns < 8; ns++) {
                int nt = ns >> 1, hf = ns & 1;
                mma_f16(sacc[ns], a, bh4[nt][hf], bh4[nt][hf + 2]);
            }
        }

        #pragma unroll
        for (int rw = 0; rw < 2; rw++) {
            float mx = -1e30f;
            #pragma unroll
            for (int nf = 0; nf < 8; nf++)
                mx = fmaxf(mx, fmaxf(sacc[nf][2 * rw], sacc[nf][2 * rw + 1]));
            mx = fmaxf(mx, __shfl_xor_sync(0xffffffffu, mx, 1));
            mx = fmaxf(mx, __shfl_xor_sync(0xffffffffu, mx, 2));
            float mn = fmaxf(m_[rw], mx);
            float corr = __expf(m_[rw] - mn);
            m_[rw] = mn;
            float sum = 0.f;
            int prow = wrow + rw * 8 + g;
            #pragma unroll
            for (int nf = 0; nf < 8; nf++) {
                float p0 = __expf(sacc[nf][2 * rw] - mn);
                float p1 = __expf(sacc[nf][2 * rw + 1] - mn);
                sum += p0 + p1;
                __half2 ph; ph.x = __float2half_rn(p0); ph.y = __float2half_rn(p1);
                unsigned pa = psb + (unsigned)(prow * PS2 + nf * 8 + tg * 2) * 2;
                asm volatile("st.shared.b32 [%0], %1;" :: "r"(pa), "r"(*(unsigned*)&ph));
            }
            sum += __shfl_xor_sync(0xffffffffu, sum, 1);
            sum += __shfl_xor_sync(0xffffffffu, sum, 2);
            l_[rw] = l_[rw] * corr + sum;
            #pragma unroll
            for (int nf = 0; nf < 8; nf++) {
                o[nf][2 * rw]     *= corr;
                o[nf][2 * rw + 1] *= corr;
            }
        }
        __syncwarp();

        #pragma unroll
        for (int kc2 = 0; kc2 < 4; kc2++) {
            int k0 = kc2 * 16;
            unsigned a[4], bv[4][4];
            ldsm4(a, psb + (unsigned)((wrow + lrow) * PS2 + k0 + lko) * 2);
            #pragma unroll
            for (int nt = 0; nt < 4; nt++)
                ldsm4(bv[nt], vsp + (unsigned)((nt * 16 + lrow) * VS2 + k0 + lko) * 2);
            #pragma unroll
            for (int ns = 0; ns < 8; ns++) {
                int nt = ns >> 1, hf = ns & 1;
                mma_f16(o[ns], a, bv[nt][hf], bv[nt][hf + 2]);
            }
        }
        __syncthreads();
        if (it + 2 < NIT) load_kv(s, (it + 2) * 64);
    }

    #pragma unroll
    for (int rw = 0; rw < 2; rw++) {
        float inv = 1.f / l_[rw];
        int row = b * NQ + q0 + wrow + rw * 8 + g;
        #pragma unroll
        for (int nf = 0; nf < 8; nf++) {
            int col = h * HD + nf * 8 + tg * 2;
            __half2 hv;
            hv.x = __float2half_rn(o[nf][2 * rw] * inv);
            hv.y = __float2half_rn(o[nf][2 * rw + 1] * inv);
            *(__half2*)&outh[(size_t)row * DI + col] = hv;
        }
    }
}

// ---------------- host launcher ----------------
static void fill_ws(WsArgs& wa, const float** Ws, __half* wth, __half* wtl,
                    const int* Ks, const int* Ns, const int* offs, int n, int& total) {
    int acc0 = 0;
    for (int i = 0; i < n; i++) {
        wa.W[i] = Ws[i]; wa.th[i] = wth + offs[i]; wa.tl[i] = wtl + offs[i];
        wa.K[i] = Ks[i]; wa.N[i] = Ns[i];
        wa.start[i] = acc0;
        acc0 += (Ks[i] / 32) * (Ns[i] / 32);
    }
    for (int i = n; i < 9; i++) wa.start[i] = 0x7FFFFFFF;
    total = acc0;
}

extern "C" void kernel_launch(void* const* d_in, const int* in_sizes, int n_in,
                              void* d_out, int out_size) {
    const float* coords = (const float*)d_in[0];
    const float* values = (const float*)d_in[1];
    const float* Lv     = (const float*)d_in[2];
    const float* Lc     = (const float*)d_in[3];
    const float* lam    = (const float*)d_in[4];
    const float* lvn_g  = (const float*)d_in[5];
    const float* lvn_b  = (const float*)d_in[6];
    const float* lcn_g  = (const float*)d_in[7];
    const float* lcn_b  = (const float*)d_in[8];
    const float* ck_w   = (const float*)d_in[9];
    const float* ck_b   = (const float*)d_in[10];
    const float* ck_g   = (const float*)d_in[11];
    const float* cq_w   = (const float*)d_in[12];
    const float* cq_b   = (const float*)d_in[13];
    const float* cq_g   = (const float*)d_in[14];
    const float* vq_w   = (const float*)d_in[15];
    const float* vq_b   = (const float*)d_in[16];
    const float* vq_g   = (const float*)d_in[17];
    const float* vk_w   = (const float*)d_in[18];
    const float* vk_b   = (const float*)d_in[19];
    const float* op_w   = (const float*)d_in[20];
    const float* op_b   = (const float*)d_in[21];
    const float* oln_g  = (const float*)d_in[22];
    const float* oln_b  = (const float*)d_in[23];
    const float* m1_w   = (const float*)d_in[24];
    const float* m1_b   = (const float*)d_in[25];
    const float* m2_w   = (const float*)d_in[26];
    const float* m2_b   = (const float*)d_in[27];
    const float* m3_w   = (const float*)d_in[28];
    const float* m3_b   = (const float*)d_in[29];
    float* out = (float*)d_out;

    float *vkb, *kcb, *qvb, *qcb, *yb;
    cudaGetSymbolAddress((void**)&vkb, g_vk);
    cudaGetSymbolAddress((void**)&kcb, g_kc);
    cudaGetSymbolAddress((void**)&qvb, g_qv);
    cudaGetSymbolAddress((void**)&qcb, g_qc);
    cudaGetSymbolAddress((void**)&yb,  g_y);
    __half *sLvh, *sLvl, *sLch, *sLcl, *valh, *vall, *crdh, *crdl;
    __half *atth, *ybsh, *ybsl, *h1h, *h2h, *wth, *wtl;
    __half *qvh, *qch, *kf, *vt;
    cudaGetSymbolAddress((void**)&sLvh, g_sLv_h); cudaGetSymbolAddress((void**)&sLvl, g_sLv_l);
    cudaGetSymbolAddress((void**)&sLch, g_sLc_h); cudaGetSymbolAddress((void**)&sLcl, g_sLc_l);
    cudaGetSymbolAddress((void**)&valh, g_val_h); cudaGetSymbolAddress((void**)&vall, g_val_l);
    cudaGetSymbolAddress((void**)&crdh, g_crd_h); cudaGetSymbolAddress((void**)&crdl, g_crd_l);
    cudaGetSymbolAddress((void**)&atth, g_att_h);
    cudaGetSymbolAddress((void**)&ybsh, g_ybs_h); cudaGetSymbolAddress((void**)&ybsl, g_ybs_l);
    cudaGetSymbolAddress((void**)&h1h,  g_h1_h);
    cudaGetSymbolAddress((void**)&h2h,  g_h2_h);
    cudaGetSymbolAddress((void**)&wth,  g_wth);   cudaGetSymbolAddress((void**)&wtl,  g_wtl);
    cudaGetSymbolAddress((void**)&qvh,  g_qvh);   cudaGetSymbolAddress((void**)&qch,  g_qch);
    cudaGetSymbolAddress((void**)&kf,   g_kf);    cudaGetSymbolAddress((void**)&vt,   g_vt);

    const int BNL = BATCH * NL;
    const int BNQ = BATCH * NQ;
    const int GSMC = 3 * 4 * PLANE_B;  // 122880
    const int GSM1 = 3 * 2 * PLANE_B;  // 61440
    const int ATTN_SMEM = 128 * QS2 * 2 + 2 * 64 * QS2 * 2 + 2 * 64 * VS2 * 2 + 128 * PS2 * 2;
    cudaFuncSetAttribute((const void*)gemm_h<0, true>,  cudaFuncAttributeMaxDynamicSharedMemorySize, GSMC);
    cudaFuncSetAttribute((const void*)gemm_h<0, false>, cudaFuncAttributeMaxDynamicSharedMemorySize, GSM1);
    cudaFuncSetAttribute((const void*)gemm_h<1, false>, cudaFuncAttributeMaxDynamicSharedMemorySize, GSM1);
    cudaFuncSetAttribute(attn_h16, cudaFuncAttributeMaxDynamicSharedMemorySize, ATTN_SMEM);

    // side stream + events (host-side only)
    cudaStream_t s1;
    cudaStreamCreateWithFlags(&s1, cudaStreamNonBlocking);
    cudaEvent_t eF, eW, eK, eW2;
    cudaEventCreateWithFlags(&eF,  cudaEventDisableTiming);
    cudaEventCreateWithFlags(&eW,  cudaEventDisableTiming);
    cudaEventCreateWithFlags(&eK,  cudaEventDisableTiming);
    cudaEventCreateWithFlags(&eW2, cudaEventDisableTiming);

    // fork: latent/K branch starts immediately
    cudaEventRecord(eF, 0);
    cudaStreamWaitEvent(s1, eF, 0);
    layernorm_split<<<BNL, 256, 0, s1>>>(Lv, lvn_g, lvn_b, sLvh, sLvl, DV, 1e-5f);
    layernorm_split<<<BNL, 128, 0, s1>>>(Lc, lcn_g, lcn_b, sLch, sLcl, DC, 1e-5f);

    // weight split PHASE 1 on main: projection weights only (~6 us)
    {
        WsArgs wa; int tot;
        const float* Ws[4] = {ck_w, cq_w, vq_w, vk_w};
        int Ks[4] = {DC, DC, DV, DV};
        int Ns[4] = {DI, DI, DI, 2 * DI};
        int offs[4] = {OFF_CKW, OFF_CQW, OFF_VQW, OFF_VKW};
        fill_ws(wa, Ws, wth, wtl, Ks, Ns, offs, 4, tot);
        wtsplit_all<<<tot, dim3(32, 8)>>>(wa);
    }
    cudaEventRecord(eW, 0);

    // latent/K branch on s1 (vk single-pass; ck compensated)
    cudaStreamWaitEvent(s1, eW, 0);
    gemm_h<0, false><<<dim3(8, 32), 256, GSM1, s1>>>(sLvh, (__half*)0, wth + OFF_VKW, (__half*)0,
                                                     vk_b, vkb, (__half*)0, BNL, DV, 2 * DI);
    gemm_h<0, true><<<dim3(4, 32), 256, GSMC, s1>>>(sLch, sLcl, wth + OFF_CKW, wtl + OFF_CKW,
                                                    ck_b, kcb, (__half*)0, BNL, DC, DI);
    rmsnorm_kernel<<<BNL, 256, 0, s1>>>(kcb, ck_g, DI, 1e-6f, 1.0f);
    kcomb_kernel<<<dim3(NL, BATCH), 256, 0, s1>>>(kcb, vkb, lam, kf);
    vtrans_kernel<<<dim3(NL/32, 2, BATCH*NH), dim3(32, 8), 0, s1>>>(vkb, vt);
    cudaEventRecord(eK, s1);

    // weight split PHASE 2 on s1 (MLP-path weights) — overlaps attention on main;
    // main waits eW2 before the op GEMM (first consumer of these weights).
    {
        WsArgs wa; int tot;
        const float* Ws[4] = {op_w, m1_w, m2_w, m3_w};
        int Ks[4] = {DI, DV, DF, DF};
        int Ns[4] = {DV, DF, DF, DV};
        int offs[4] = {OFF_OPW, OFF_M1W, OFF_M2W, OFF_M3W};
        fill_ws(wa, Ws, wth, wtl, Ks, Ns, offs, 4, tot);
        wtsplit_all<<<tot, dim3(32, 8), 0, s1>>>(wa);
    }
    cudaEventRecord(eW2, s1);

    // q branch on main stream (starts right after phase 1; vq single-pass, cq compensated)
    split_copy_h<<<BNQ * DV / 4 / 256, 256>>>(values, valh, vall, BNQ * DV / 4);
    split_copy_h<<<BNQ * DC / 4 / 256, 256>>>(coords, crdh, crdl, BNQ * DC / 4);
    gemm_h<0, false><<<dim3(4, 128), 256, GSM1>>>(valh, (__half*)0, wth + OFF_VQW, (__half*)0,
                                                  vq_b, qvb, (__half*)0, BNQ, DV, DI);
    gemm_h<0, true><<<dim3(4, 128), 256, GSMC>>>(crdh, crdl, wth + OFF_CQW, wtl + OFF_CQW,
                                                 cq_b, qcb, (__half*)0, BNQ, DC, DI);
    rmsnorm_h<<<BNQ, 256>>>(qvb, vq_g, qvh, DI, 1e-6f, 0.125f);
    rmsnorm_h<<<BNQ, 256>>>(qcb, cq_g, qch, DI, 1e-6f, 0.125f);

    // join K branch, attention (phase 2 weight split overlaps this on s1)
    cudaStreamWaitEvent(0, eK, 0);
    attn_h16<<<dim3(NQ/128, NH, BATCH), 256, ATTN_SMEM>>>(qch, qvh, kf, vt, atth);

    // join phase-2 weights, then MLP tail (R11 8-warp config)
    cudaStreamWaitEvent(0, eW2, 0);
    gemm_h<0, false><<<dim3(4, 128), 256, GSM1>>>(atth, (__half*)0, wth + OFF_OPW, (__half*)0,
                                                  op_b, yb, (__half*)0, BNQ, DI, DV);
    layernorm_split<<<BNQ, 256>>>(yb, oln_g, oln_b, ybsh, ybsl, DV, 1e-5f);
    gemm_h<1, false><<<dim3(16, 128), 256, GSM1>>>(ybsh, (__half*)0, wth + OFF_M1W, (__half*)0,
                                                   m1_b, (float*)0, h1h, BNQ, DV, DF);
    gemm_h<1, false><<<dim3(16, 128), 256, GSM1>>>(h1h, (__half*)0, wth + OFF_M2W, (__half*)0,
                                                   m2_b, (float*)0, h2h, BNQ, DF, DF);
    gemm_h<0, false><<<dim3(4, 128), 256, GSM1>>>(h2h, (__half*)0, wth + OFF_M3W, (__half*)0,
                                                  m3_b, out, (__half*)0, BNQ, DF, DV);
}

// round 14
// speedup vs baseline: 1.0085x; 1.0035x over previous
#include <cuda_runtime.h>
#include <cuda_fp16.h>
#include <math.h>
#include <cstdint>

#define BATCH 4
#define NQ 4096
#define NL 1024
#define DV 512
#define DC 128
#define DI 512
#define DF 2048
#define NH 8
#define HD 64

// ---------------- device scratch ----------------
__device__ float g_vk [BATCH * NL * (2 * DI)];
__device__ float g_kc [BATCH * NL * DI];
__device__ float g_qv [BATCH * NQ * DI];
__device__ float g_qc [BATCH * NQ * DI];
__device__ float g_y  [BATCH * NQ * DV];
__device__ __align__(16) __half g_qvh[BATCH * NQ * DI], g_qch[BATCH * NQ * DI];
__device__ __align__(16) __half g_kf [BATCH * NH * NL * 128];
__device__ __align__(16) __half g_vt [BATCH * NH * 64 * NL];
__device__ __align__(16) __half g_sLv_h[BATCH * NL * DV];
__device__ __align__(16) __half g_sLc_h[BATCH * NL * DC], g_sLc_l[BATCH * NL * DC];
__device__ __align__(16) __half g_val_h[BATCH * NQ * DV];
__device__ __align__(16) __half g_crd_h[BATCH * NQ * DC], g_crd_l[BATCH * NQ * DC];
__device__ __align__(16) __half g_att_h[BATCH * NQ * DI];
__device__ __align__(16) __half g_ybs_h[BATCH * NQ * DV], g_ybs_l[BATCH * NQ * DV];
__device__ __align__(16) __half g_h1_h[BATCH * NQ * DF];
__device__ __align__(16) __half g_h2_h[BATCH * NQ * DF];
__device__ __align__(16) __half g_wth[7471104], g_wtl[7471104];

#define OFF_CKW 0
#define OFF_CQW 65536
#define OFF_VQW 131072
#define OFF_VKW 393216
#define OFF_OPW 917504
#define OFF_M1W 1179648
#define OFF_M2W 2228224
#define OFF_M3W 6422528

// ---------------- helpers ----------------
__device__ __forceinline__ float gelu_f(float x) {
    float x3 = x * x * x;
    return 0.5f * x * (1.0f + tanhf(0.7978845608028654f * (x + 0.044715f * x3)));
}
__device__ __forceinline__ void split2h(float x, __half& h, __half& l) {
    h = __float2half_rn(x);
    l = __float2half_rn(x - __half2float(h));
}
__device__ __forceinline__ void mma_f16(float* c, const unsigned* a, unsigned b0, unsigned b1) {
    asm volatile(
        "mma.sync.aligned.m16n8k16.row.col.f32.f16.f16.f32 "
        "{%0,%1,%2,%3},{%4,%5,%6,%7},{%8,%9},{%0,%1,%2,%3};"
        : "+f"(c[0]), "+f"(c[1]), "+f"(c[2]), "+f"(c[3])
        : "r"(a[0]), "r"(a[1]), "r"(a[2]), "r"(a[3]), "r"(b0), "r"(b1));
}
__device__ __forceinline__ void ldsm4(unsigned* r, unsigned addr) {
    asm volatile("ldmatrix.sync.aligned.m8n8.x4.shared.b16 {%0,%1,%2,%3}, [%4];"
        : "=r"(r[0]), "=r"(r[1]), "=r"(r[2]), "=r"(r[3]) : "r"(addr));
}
__device__ __forceinline__ void cpa16(unsigned dst, const void* src) {
    asm volatile("cp.async.cg.shared.global [%0], [%1], 16;" :: "r"(dst), "l"(src));
}
__device__ __forceinline__ void cpa_commit() { asm volatile("cp.async.commit_group;"); }
__device__ __forceinline__ unsigned sh_addr(const void* p) {
    return (unsigned)__cvta_generic_to_shared(p);
}

// ---------------- producers ----------------
__global__ void split_copy_h(const float* __restrict__ x, __half* __restrict__ h,
                             __half* __restrict__ l, int n4) {
    int i = blockIdx.x * blockDim.x + threadIdx.x;
    if (i < n4) {
        float4 v = ((const float4*)x)[i];
        int b = i * 4;
        __half h0, l0; split2h(v.x, h0, l0); h[b] = h0; l[b] = l0;
        split2h(v.y, h0, l0); h[b+1] = h0; l[b+1] = l0;
        split2h(v.z, h0, l0); h[b+2] = h0; l[b+2] = l0;
        split2h(v.w, h0, l0); h[b+3] = h0; l[b+3] = l0;
    }
}

// hi-only fp16 convert (for operands whose lo part is never consumed)
__global__ void convert_h(const float* __restrict__ x, __half* __restrict__ h, int n4) {
    int i = blockIdx.x * blockDim.x + threadIdx.x;
    if (i < n4) {
        float4 v = ((const float4*)x)[i];
        __half2 a, b;
        a.x = __float2half_rn(v.x); a.y = __float2half_rn(v.y);
        b.x = __float2half_rn(v.z); b.y = __float2half_rn(v.w);
        *(__half2*)&h[i * 4]     = a;
        *(__half2*)&h[i * 4 + 2] = b;
    }
}

// batched weight split+transpose (subset of up to 8 layers per launch)
struct WsArgs {
    const float* W[8];
    __half* th[8];
    __half* tl[8];
    int K[8], N[8];
    int start[9];
};
__global__ void wtsplit_all(WsArgs a) {
    __shared__ float t[32][33];
    int bid = blockIdx.x;
    int l = 0;
    #pragma unroll
    for (int i = 1; i < 8; i++) if (bid >= a.start[i]) l = i;
    int tidx = bid - a.start[l];
    int K = a.K[l], N = a.N[l];
    int ntn = N >> 5;
    int k0 = (tidx / ntn) << 5;
    int n0 = (tidx % ntn) << 5;
    const float* W = a.W[l];
    __half* th = a.th[l];
    __half* tl = a.tl[l];
    int tx = threadIdx.x, ty = threadIdx.y;
    for (int dy = ty; dy < 32; dy += 8)
        t[dy][tx] = W[(size_t)(k0 + dy) * N + n0 + tx];
    __syncthreads();
    for (int rr = ty; rr < 32; rr += 8) {
        __half h, lo; split2h(t[tx][rr], h, lo);
        th[(size_t)(n0 + rr) * K + k0 + tx] = h;
        tl[(size_t)(n0 + rr) * K + k0 + tx] = lo;
    }
}

template <bool SPLIT>
__global__ void layernorm_t(const float* __restrict__ x, const float* __restrict__ g,
                            const float* __restrict__ b, __half* __restrict__ yh,
                            __half* __restrict__ yl, int D, float eps) {
    int row = blockIdx.x;
    const float* xr = x + (size_t)row * D;
    float s = 0.f, ss = 0.f;
    for (int i = threadIdx.x; i < D; i += blockDim.x) { float v = xr[i]; s += v; ss += v * v; }
    __shared__ float rs[32], rss[32];
    #pragma unroll
    for (int off = 16; off; off >>= 1) {
        s  += __shfl_xor_sync(0xffffffffu, s,  off);
        ss += __shfl_xor_sync(0xffffffffu, ss, off);
    }
    int w = threadIdx.x >> 5, l = threadIdx.x & 31;
    if (l == 0) { rs[w] = s; rss[w] = ss; }
    __syncthreads();
    int nw = blockDim.x >> 5;
    if (threadIdx.x < 32) {
        s  = (l < nw) ? rs[l]  : 0.f;
        ss = (l < nw) ? rss[l] : 0.f;
        #pragma unroll
        for (int off = 16; off; off >>= 1) {
            s  += __shfl_xor_sync(0xffffffffu, s,  off);
            ss += __shfl_xor_sync(0xffffffffu, ss, off);
        }
        if (l == 0) { rs[0] = s; rss[0] = ss; }
    }
    __syncthreads();
    float mean = rs[0] / (float)D;
    float inv  = rsqrtf(rss[0] / (float)D - mean * mean + eps);
    for (int i = threadIdx.x; i < D; i += blockDim.x) {
        float v = (xr[i] - mean) * inv * g[i] + b[i];
        if (SPLIT) {
            __half h, lo; split2h(v, h, lo);
            yh[(size_t)row * D + i] = h; yl[(size_t)row * D + i] = lo;
        } else {
            yh[(size_t)row * D + i] = __float2half_rn(v);
        }
    }
}

__global__ void rmsnorm_kernel(float* __restrict__ x, const float* __restrict__ g,
                               int D, float eps, float scale) {
    int row = blockIdx.x;
    float* xr = x + (size_t)row * D;
    float ss = 0.f;
    for (int i = threadIdx.x; i < D; i += blockDim.x) { float v = xr[i]; ss += v * v; }
    __shared__ float rss[32];
    #pragma unroll
    for (int off = 16; off; off >>= 1) ss += __shfl_xor_sync(0xffffffffu, ss, off);
    int w = threadIdx.x >> 5, l = threadIdx.x & 31;
    if (l == 0) rss[w] = ss;
    __syncthreads();
    int nw = blockDim.x >> 5;
    if (threadIdx.x < 32) {
        ss = (l < nw) ? rss[l] : 0.f;
        #pragma unroll
        for (int off = 16; off; off >>= 1) ss += __shfl_xor_sync(0xffffffffu, ss, off);
        if (l == 0) rss[0] = ss;
    }
    __syncthreads();
    float inv = rsqrtf(rss[0] / (float)D + eps) * scale;
    for (int i = threadIdx.x; i < D; i += blockDim.x)
        xr[i] = xr[i] * inv * g[i];
}

__global__ void rmsnorm_h(const float* __restrict__ x, const float* __restrict__ g,
                          __half* __restrict__ y, int D, float eps, float scale) {
    int row = blockIdx.x;
    const float* xr = x + (size_t)row * D;
    float ss = 0.f;
    for (int i = threadIdx.x; i < D; i += blockDim.x) { float v = xr[i]; ss += v * v; }
    __shared__ float rss[32];
    #pragma unroll
    for (int off = 16; off; off >>= 1) ss += __shfl_xor_sync(0xffffffffu, ss, off);
    int w = threadIdx.x >> 5, l = threadIdx.x & 31;
    if (l == 0) rss[w] = ss;
    __syncthreads();
    int nw = blockDim.x >> 5;
    if (threadIdx.x < 32) {
        ss = (l < nw) ? rss[l] : 0.f;
        #pragma unroll
        for (int off = 16; off; off >>= 1) ss += __shfl_xor_sync(0xffffffffu, ss, off);
        if (l == 0) rss[0] = ss;
    }
    __syncthreads();
    float inv = rsqrtf(rss[0] / (float)D + eps) * scale;
    for (int i = threadIdx.x; i < D; i += blockDim.x)
        y[(size_t)row * D + i] = __float2half_rn(xr[i] * inv * g[i]);
}

__global__ void kcomb_kernel(const float* __restrict__ kc, const float* __restrict__ vk,
                             const float* __restrict__ lamp, __half* __restrict__ kf) {
    int j = blockIdx.x, b = blockIdx.y;
    int tid = threadIdx.x;
    float lam = lamp[0];
    int e = tid * 4;
    int h = e >> 7, dd = e & 127;
    float4 v;
    if (dd < 64)
        v = *(const float4*)&kc[((size_t)(b * NL + j)) * DI + h * 64 + dd];
    else {
        v = *(const float4*)&vk[((size_t)(b * NL + j)) * (2 * DI) + DI + h * 64 + (dd - 64)];
        v.x *= lam; v.y *= lam; v.z *= lam; v.w *= lam;
    }
    __half* dst = kf + ((size_t)((b * NH + h) * NL + j)) * 128 + dd;
    dst[0] = __float2half_rn(v.x); dst[1] = __float2half_rn(v.y);
    dst[2] = __float2half_rn(v.z); dst[3] = __float2half_rn(v.w);
}

__global__ void vtrans_kernel(const float* __restrict__ vk, __half* __restrict__ vt) {
    __shared__ float t[32][33];
    int bh = blockIdx.z; int b = bh >> 3; int h = bh & 7;
    int j0 = blockIdx.x * 32, d0 = blockIdx.y * 32;
    int tx = threadIdx.x, ty = threadIdx.y;
    const float* s = vk + ((size_t)(b * NL + j0)) * (2 * DI) + h * HD + d0;
    for (int dy = ty; dy < 32; dy += 8)
        t[dy][tx] = s[(size_t)dy * (2 * DI) + tx];
    __syncthreads();
    for (int dy = ty; dy < 32; dy += 8)
        vt[((size_t)(bh * 64 + d0 + dy)) * NL + j0 + tx] = __float2half_rn(t[tx][dy]);
}

// ---------------- fp16 GEMM 128x128x32, 8 warps (warp tile 32x64) ----------------
// COMP: 2-stage pipeline (82KB smem -> 2 CTA/SM).  non-COMP: 3-stage (61KB).
#define RSTR 40
#define PLANE_B (128 * RSTR * 2)  // 10240
template <int EPI, bool COMP>    // EPI: 0=bias fp32, 1=bias+gelu fp16
__global__ void __launch_bounds__(256, 2) gemm_h(
    const __half* __restrict__ Ah, const __half* __restrict__ Al,
    const __half* __restrict__ Bh, const __half* __restrict__ Bl,
    const float* __restrict__ bias,
    float* __restrict__ Cf, __half* __restrict__ Chh,
    int M, int K, int N) {
    extern __shared__ char smc[];
    const unsigned smb = sh_addr(smc);
    constexpr int NSTG = COMP ? 2 : 3;
    constexpr unsigned STAGE_B = (COMP ? 4 : 2) * PLANE_B;
    const int tid = threadIdx.x, warp = tid >> 5, lane = tid & 31;
    const int bm = blockIdx.y * 128, bn = blockIdx.x * 128;
    const int wm = (warp & 3) * 32, wn = (warp >> 2) * 64;
    const int g = lane >> 2, tg = lane & 3;
    const int KT = K >> 5;

    float acc[2][8][4];
    #pragma unroll
    for (int i = 0; i < 2; i++)
        #pragma unroll
        for (int j = 0; j < 8; j++)
            #pragma unroll
            for (int k = 0; k < 4; k++) acc[i][j][k] = 0.f;

    auto load_stage = [&](int s, int kt) {
        if (kt < KT) {
            unsigned base = smb + s * STAGE_B;
            #pragma unroll
            for (int i = 0; i < 2; i++) {
                int idx = tid + i * 256;
                int r = idx >> 2, c = idx & 3;
                size_t goA = (size_t)(bm + r) * K + kt * 32 + c * 8;
                size_t goB = (size_t)(bn + r) * K + kt * 32 + c * 8;
                unsigned so = (unsigned)(r * 80 + c * 16);
                cpa16(base + so, Ah + goA);
                cpa16(base + PLANE_B + so, Bh + goB);
                if (COMP) {
                    cpa16(base + 2 * PLANE_B + so, Al + goA);
                    cpa16(base + 3 * PLANE_B + so, Bl + goB);
                }
            }
            cpa_commit();
        }
    };
    load_stage(0, 0);
    if (KT > 1) load_stage(1, 1);

    const int lrow = lane & 15;
    const int lko = (lane >> 4) * 8;

    for (int kt = 0; kt < KT; kt++) {
        if (kt < KT - 1) asm volatile("cp.async.wait_group 1;" ::: "memory");
        else             asm volatile("cp.async.wait_group 0;" ::: "memory");
        __syncthreads();
        int s = kt % NSTG;
        if (!COMP && kt + 2 < KT) load_stage((kt + 2) % 3, kt + 2);
        unsigned aB = smb + s * STAGE_B;
        unsigned bB = aB + PLANE_B;
        #pragma unroll
        for (int ks2 = 0; ks2 < 2; ks2++) {
            int k0 = ks2 * 16;
            unsigned ah[2][4], bh[4][4];
            #pragma unroll
            for (int mt = 0; mt < 2; mt++)
                ldsm4(ah[mt], aB + (unsigned)((wm + mt * 16 + lrow) * RSTR + k0 + lko) * 2);
            #pragma unroll
            for (int nt = 0; nt < 4; nt++)
                ldsm4(bh[nt], bB + (unsigned)((wn + nt * 16 + lrow) * RSTR + k0 + lko) * 2);
            #pragma unroll
            for (int ns = 0; ns < 8; ns++) {
                int nt = ns >> 1, hf = ns & 1;
                unsigned b0 = bh[nt][hf], b1 = bh[nt][hf + 2];
                mma_f16(acc[0][ns], ah[0], b0, b1);
                mma_f16(acc[1][ns], ah[1], b0, b1);
            }
            if (COMP) {
                unsigned al[2][4], bl[4][4];
                #pragma unroll
                for (int mt = 0; mt < 2; mt++)
                    ldsm4(al[mt], aB + 2 * PLANE_B + (unsigned)((wm + mt * 16 + lrow) * RSTR + k0 + lko) * 2);
                #pragma unroll
                for (int nt = 0; nt < 4; nt++)
                    ldsm4(bl[nt], bB + 2 * PLANE_B + (unsigned)((wn + nt * 16 + lrow) * RSTR + k0 + lko) * 2);
                #pragma unroll
                for (int ns = 0; ns < 8; ns++) {
                    int nt = ns >> 1, hf = ns & 1;
                    unsigned bl0 = bl[nt][hf], bl1 = bl[nt][hf + 2];
                    unsigned bh0 = bh[nt][hf], bh1 = bh[nt][hf + 2];
                    mma_f16(acc[0][ns], ah[0], bl0, bl1);
                    mma_f16(acc[1][ns], ah[1], bl0, bl1);
                    mma_f16(acc[0][ns], al[0], bh0, bh1);
                    mma_f16(acc[1][ns], al[1], bh0, bh1);
                }
            }
        }
        __syncthreads();  // convergence barrier (load-bearing, see R6 post-mortem)
        if (COMP && kt + 2 < KT) load_stage(s, kt + 2);  // refill the stage just consumed
    }

    #pragma unroll
    for (int mf = 0; mf < 2; mf++) {
        int row = bm + wm + mf * 16 + g;
        #pragma unroll
        for (int nf = 0; nf < 8; nf++) {
            int col = bn + wn + nf * 8 + tg * 2;
            float b0v = bias[col], b1v = bias[col + 1];
            float v00 = acc[mf][nf][0] + b0v, v01 = acc[mf][nf][1] + b1v;
            float v10 = acc[mf][nf][2] + b0v, v11 = acc[mf][nf][3] + b1v;
            if (EPI == 1) {
                __half2 p0, p1;
                p0.x = __float2half_rn(gelu_f(v00)); p0.y = __float2half_rn(gelu_f(v01));
                p1.x = __float2half_rn(gelu_f(v10)); p1.y = __float2half_rn(gelu_f(v11));
                *(__half2*)&Chh[(size_t)row * N + col]       = p0;
                *(__half2*)&Chh[(size_t)(row + 8) * N + col] = p1;
            } else {
                *(float2*)&Cf[(size_t)row * N + col]       = make_float2(v00, v01);
                *(float2*)&Cf[(size_t)(row + 8) * N + col] = make_float2(v10, v11);
            }
        }
    }
}

// ---------------- fp16 dual-score flash attention ----------------
#define QS2 136
#define VS2 72
#define PS2 72
__global__ void __launch_bounds__(256) attn_h16(const __half* __restrict__ Qc,
                                                const __half* __restrict__ Qv,
                                                const __half* __restrict__ Kf,
                                                const __half* __restrict__ Vt,
                                                __half* __restrict__ outh) {
    extern __shared__ char smc[];
    const unsigned smb = sh_addr(smc);
    const unsigned qsb = smb;
    const unsigned ksb = qsb + 128 * QS2 * 2;
    const unsigned vsb = ksb + 2 * 64 * QS2 * 2;
    const unsigned psb = vsb + 2 * 64 * VS2 * 2;
    const int tid = threadIdx.x, warp = tid >> 5, lane = tid & 31;
    const int g = lane >> 2, tg = lane & 3;
    const int q0 = blockIdx.x * 128, h = blockIdx.y, b = blockIdx.z;
    const int bh = b * NH + h;

    const __half* qcb_ = Qc + ((size_t)(b * NQ + q0)) * DI + h * HD;
    const __half* qvb_ = Qv + ((size_t)(b * NQ + q0)) * DI + h * HD;
    #pragma unroll
    for (int i = 0; i < 8; i++) {
        int idx = tid + i * 256;
        int r = idx >> 4, c = idx & 15;
        const __half* src = (c < 8) ? (qcb_ + (size_t)r * DI + c * 8)
                                    : (qvb_ + (size_t)r * DI + (c - 8) * 8);
        cpa16(qsb + (unsigned)(r * QS2 + c * 8) * 2, src);
    }
    cpa_commit();

    const __half* kfb = Kf + (size_t)bh * NL * 128;
    const __half* vtb = Vt + (size_t)bh * 64 * NL;
    auto load_kv = [&](int s, int m0) {
        unsigned ks_ = ksb + s * (64 * QS2 * 2);
        unsigned vs_ = vsb + s * (64 * VS2 * 2);
        #pragma unroll
        for (int i = 0; i < 4; i++) {
            int idx = tid + i * 256;
            int r = idx >> 4, c = idx & 15;
            cpa16(ks_ + (unsigned)(r * QS2 + c * 8) * 2, kfb + (size_t)(m0 + r) * 128 + c * 8);
        }
        #pragma unroll
        for (int i = 0; i < 2; i++) {
            int idx = tid + i * 256;
            int r = idx >> 3, c = idx & 7;
            cpa16(vs_ + (unsigned)(r * VS2 + c * 8) * 2, vtb + (size_t)r * NL + m0 + c * 8);
        }
        cpa_commit();
    };
    load_kv(0, 0);
    load_kv(1, 64);

    float m_[2] = {-1e30f, -1e30f}, l_[2] = {0.f, 0.f};
    float o[8][4];
    #pragma unroll
    for (int i = 0; i < 8; i++)
        #pragma unroll
        for (int j = 0; j < 4; j++) o[i][j] = 0.f;

    const int wrow = warp * 16;
    const int lrow = lane & 15;
    const int lko = (lane >> 4) * 8;
    const int NIT = NL / 64;

    for (int it = 0; it < NIT; it++) {
        if (it < NIT - 1) asm volatile("cp.async.wait_group 1;" ::: "memory");
        else              asm volatile("cp.async.wait_group 0;" ::: "memory");
        __syncthreads();
        int s = it & 1;
        unsigned ksp = ksb + s * (64 * QS2 * 2);
        unsigned vsp = vsb + s * (64 * VS2 * 2);

        float sacc[8][4];
        #pragma unroll
        for (int i = 0; i < 8; i++)
            #pragma unroll
            for (int j = 0; j < 4; j++) sacc[i][j] = 0.f;
        #pragma unroll
        for (int kc2 = 0; kc2 < 8; kc2++) {
            int k0 = kc2 * 16;
            unsigned a[4], bh4[4][4];
            ldsm4(a, qsb + (unsigned)((wrow + lrow) * QS2 + k0 + lko) * 2);
            #pragma unroll
            for (int nt = 0; nt < 4; nt++)
                ldsm4(bh4[nt], ksp + (unsigned)((nt * 16 + lrow) * QS2 + k0 + lko) * 2);
            #pragma unroll
            for (int ns = 0; ns < 8; ns++) {
                int nt = ns >> 1, hf = ns & 1;
                mma_f16(sacc[ns], a, bh4[nt][hf], bh4[nt][hf + 2]);
            }
        }

        #pragma unroll
        for (int rw = 0; rw < 2; rw++) {
            float mx = -1e30f;
            #pragma unroll
            for (int nf = 0; nf < 8; nf++)
                mx = fmaxf(mx, fmaxf(sacc[nf][2 * rw], sacc[nf][2 * rw + 1]));
            mx = fmaxf(mx, __shfl_xor_sync(0xffffffffu, mx, 1));
            mx = fmaxf(mx, __shfl_xor_sync(0xffffffffu, mx, 2));
            float mn = fmaxf(m_[rw], mx);
            float corr = __expf(m_[rw] - mn);
            m_[rw] = mn;
            float sum = 0.f;
            int prow = wrow + rw * 8 + g;
            #pragma unroll
            for (int nf = 0; nf < 8; nf++) {
                float p0 = __expf(sacc[nf][2 * rw] - mn);
                float p1 = __expf(sacc[nf][2 * rw + 1] - mn);
                sum += p0 + p1;
                __half2 ph; ph.x = __float2half_rn(p0); ph.y = __float2half_rn(p1);
                unsigned pa = psb + (unsigned)(prow * PS2 + nf * 8 + tg * 2) * 2;
                asm volatile("st.shared.b32 [%0], %1;" :: "r"(pa), "r"(*(unsigned*)&ph));
            }
            sum += __shfl_xor_sync(0xffffffffu, sum, 1);
            sum += __shfl_xor_sync(0xffffffffu, sum, 2);
            l_[rw] = l_[rw] * corr + sum;
            #pragma unroll
            for (int nf = 0; nf < 8; nf++) {
                o[nf][2 * rw]     *= corr;
                o[nf][2 * rw + 1] *= corr;
            }
        }
        __syncwarp();

        #pragma unroll
        for (int kc2 = 0; kc2 < 4; kc2++) {
            int k0 = kc2 * 16;
            unsigned a[4], bv[4][4];
            ldsm4(a, psb + (unsigned)((wrow + lrow) * PS2 + k0 + lko) * 2);
            #pragma unroll
            for (int nt = 0; nt < 4; nt++)
                ldsm4(bv[nt], vsp + (unsigned)((nt * 16 + lrow) * VS2 + k0 + lko) * 2);
            #pragma unroll
            for (int ns = 0; ns < 8; ns++) {
                int nt = ns >> 1, hf = ns & 1;
                mma_f16(o[ns], a, bv[nt][hf], bv[nt][hf + 2]);
            }
        }
        __syncthreads();
        if (it + 2 < NIT) load_kv(s, (it + 2) * 64);
    }

    #pragma unroll
    for (int rw = 0; rw < 2; rw++) {
        float inv = 1.f / l_[rw];
        int row = b * NQ + q0 + wrow + rw * 8 + g;
        #pragma unroll
        for (int nf = 0; nf < 8; nf++) {
            int col = h * HD + nf * 8 + tg * 2;
            __half2 hv;
            hv.x = __float2half_rn(o[nf][2 * rw] * inv);
            hv.y = __float2half_rn(o[nf][2 * rw + 1] * inv);
            *(__half2*)&outh[(size_t)row * DI + col] = hv;
        }
    }
}

// ---------------- host launcher ----------------
static void fill_ws(WsArgs& wa, const float** Ws, __half* wth, __half* wtl,
                    const int* Ks, const int* Ns, const int* offs, int n, int& total) {
    int acc0 = 0;
    for (int i = 0; i < n; i++) {
        wa.W[i] = Ws[i]; wa.th[i] = wth + offs[i]; wa.tl[i] = wtl + offs[i];
        wa.K[i] = Ks[i]; wa.N[i] = Ns[i];
        wa.start[i] = acc0;
        acc0 += (Ks[i] / 32) * (Ns[i] / 32);
    }
    for (int i = n; i < 9; i++) wa.start[i] = 0x7FFFFFFF;
    total = acc0;
}

extern "C" void kernel_launch(void* const* d_in, const int* in_sizes, int n_in,
                              void* d_out, int out_size) {
    const float* coords = (const float*)d_in[0];
    const float* values = (const float*)d_in[1];
    const float* Lv     = (const float*)d_in[2];
    const float* Lc     = (const float*)d_in[3];
    const float* lam    = (const float*)d_in[4];
    const float* lvn_g  = (const float*)d_in[5];
    const float* lvn_b  = (const float*)d_in[6];
    const float* lcn_g  = (const float*)d_in[7];
    const float* lcn_b  = (const float*)d_in[8];
    const float* ck_w   = (const float*)d_in[9];
    const float* ck_b   = (const float*)d_in[10];
    const float* ck_g   = (const float*)d_in[11];
    const float* cq_w   = (const float*)d_in[12];
    const float* cq_b   = (const float*)d_in[13];
    const float* cq_g   = (const float*)d_in[14];
    const float* vq_w   = (const float*)d_in[15];
    const float* vq_b   = (const float*)d_in[16];
    const float* vq_g   = (const float*)d_in[17];
    const float* vk_w   = (const float*)d_in[18];
    const float* vk_b   = (const float*)d_in[19];
    const float* op_w   = (const float*)d_in[20];
    const float* op_b   = (const float*)d_in[21];
    const float* oln_g  = (const float*)d_in[22];
    const float* oln_b  = (const float*)d_in[23];
    const float* m1_w   = (const float*)d_in[24];
    const float* m1_b   = (const float*)d_in[25];
    const float* m2_w   = (const float*)d_in[26];
    const float* m2_b   = (const float*)d_in[27];
    const float* m3_w   = (const float*)d_in[28];
    const float* m3_b   = (const float*)d_in[29];
    float* out = (float*)d_out;

    float *vkb, *kcb, *qvb, *qcb, *yb;
    cudaGetSymbolAddress((void**)&vkb, g_vk);
    cudaGetSymbolAddress((void**)&kcb, g_kc);
    cudaGetSymbolAddress((void**)&qvb, g_qv);
    cudaGetSymbolAddress((void**)&qcb, g_qc);
    cudaGetSymbolAddress((void**)&yb,  g_y);
    __half *sLvh, *sLch, *sLcl, *valh, *crdh, *crdl;
    __half *atth, *ybsh, *ybsl, *h1h, *h2h, *wth, *wtl;
    __half *qvh, *qch, *kf, *vt;
    cudaGetSymbolAddress((void**)&sLvh, g_sLv_h);
    cudaGetSymbolAddress((void**)&sLch, g_sLc_h); cudaGetSymbolAddress((void**)&sLcl, g_sLc_l);
    cudaGetSymbolAddress((void**)&valh, g_val_h);
    cudaGetSymbolAddress((void**)&crdh, g_crd_h); cudaGetSymbolAddress((void**)&crdl, g_crd_l);
    cudaGetSymbolAddress((void**)&atth, g_att_h);
    cudaGetSymbolAddress((void**)&ybsh, g_ybs_h); cudaGetSymbolAddress((void**)&ybsl, g_ybs_l);
    cudaGetSymbolAddress((void**)&h1h,  g_h1_h);
    cudaGetSymbolAddress((void**)&h2h,  g_h2_h);
    cudaGetSymbolAddress((void**)&wth,  g_wth);   cudaGetSymbolAddress((void**)&wtl,  g_wtl);
    cudaGetSymbolAddress((void**)&qvh,  g_qvh);   cudaGetSymbolAddress((void**)&qch,  g_qch);
    cudaGetSymbolAddress((void**)&kf,   g_kf);    cudaGetSymbolAddress((void**)&vt,   g_vt);

    const int BNL = BATCH * NL;
    const int BNQ = BATCH * NQ;
    const int GSMC = 2 * 4 * PLANE_B;  // 81920 (compensated, 2-stage)
    const int GSM1 = 3 * 2 * PLANE_B;  // 61440 (single-pass, 3-stage)
    const int ATTN_SMEM = 128 * QS2 * 2 + 2 * 64 * QS2 * 2 + 2 * 64 * VS2 * 2 + 128 * PS2 * 2;
    cudaFuncSetAttribute((const void*)gemm_h<0, true>,  cudaFuncAttributeMaxDynamicSharedMemorySize, GSMC);
    cudaFuncSetAttribute((const void*)gemm_h<0, false>, cudaFuncAttributeMaxDynamicSharedMemorySize, GSM1);
    cudaFuncSetAttribute((const void*)gemm_h<1, false>, cudaFuncAttributeMaxDynamicSharedMemorySize, GSM1);
    cudaFuncSetAttribute(attn_h16, cudaFuncAttributeMaxDynamicSharedMemorySize, ATTN_SMEM);

    // side stream + events (host-side only)
    cudaStream_t s1;
    cudaStreamCreateWithFlags(&s1, cudaStreamNonBlocking);
    cudaEvent_t eF, eW, eK, eW2;
    cudaEventCreateWithFlags(&eF,  cudaEventDisableTiming);
    cudaEventCreateWithFlags(&eW,  cudaEventDisableTiming);
    cudaEventCreateWithFlags(&eK,  cudaEventDisableTiming);
    cudaEventCreateWithFlags(&eW2, cudaEventDisableTiming);

    // fork: latent/K branch starts immediately
    cudaEventRecord(eF, 0);
    cudaStreamWaitEvent(s1, eF, 0);
    layernorm_t<false><<<BNL, 256, 0, s1>>>(Lv, lvn_g, lvn_b, sLvh, (__half*)0, DV, 1e-5f);
    layernorm_t<true><<<BNL, 128, 0, s1>>>(Lc, lcn_g, lcn_b, sLch, sLcl, DC, 1e-5f);

    // weight split PHASE 1 on main: projection weights (~6 us)
    {
        WsArgs wa; int tot;
        const float* Ws[4] = {ck_w, cq_w, vq_w, vk_w};
        int Ks[4] = {DC, DC, DV, DV};
        int Ns[4] = {DI, DI, DI, 2 * DI};
        int offs[4] = {OFF_CKW, OFF_CQW, OFF_VQW, OFF_VKW};
        fill_ws(wa, Ws, wth, wtl, Ks, Ns, offs, 4, tot);
        wtsplit_all<<<tot, dim3(32, 8)>>>(wa);
    }
    cudaEventRecord(eW, 0);

    // latent/K branch on s1 (vk single-pass; ck compensated 2-stage)
    cudaStreamWaitEvent(s1, eW, 0);
    gemm_h<0, false><<<dim3(8, 32), 256, GSM1, s1>>>(sLvh, (__half*)0, wth + OFF_VKW, (__half*)0,
                                                     vk_b, vkb, (__half*)0, BNL, DV, 2 * DI);
    gemm_h<0, true><<<dim3(4, 32), 256, GSMC, s1>>>(sLch, sLcl, wth + OFF_CKW, wtl + OFF_CKW,
                                                    ck_b, kcb, (__half*)0, BNL, DC, DI);
    rmsnorm_kernel<<<BNL, 256, 0, s1>>>(kcb, ck_g, DI, 1e-6f, 1.0f);
    kcomb_kernel<<<dim3(NL, BATCH), 256, 0, s1>>>(kcb, vkb, lam, kf);
    vtrans_kernel<<<dim3(NL/32, 2, BATCH*NH), dim3(32, 8), 0, s1>>>(vkb, vt);
    cudaEventRecord(eK, s1);

    // weight split PHASE 2 on s1 (MLP-path weights) — overlaps attention on main
    {
        WsArgs wa; int tot;
        const float* Ws[4] = {op_w, m1_w, m2_w, m3_w};
        int Ks[4] = {DI, DV, DF, DF};
        int Ns[4] = {DV, DF, DF, DV};
        int offs[4] = {OFF_OPW, OFF_M1W, OFF_M2W, OFF_M3W};
        fill_ws(wa, Ws, wth, wtl, Ks, Ns, offs, 4, tot);
        wtsplit_all<<<tot, dim3(32, 8), 0, s1>>>(wa);
    }
    cudaEventRecord(eW2, s1);

    // q branch on main stream (vq single-pass; cq compensated 2-stage)
    convert_h<<<BNQ * DV / 4 / 256, 256>>>(values, valh, BNQ * DV / 4);
    split_copy_h<<<BNQ * DC / 4 / 256, 256>>>(coords, crdh, crdl, BNQ * DC / 4);
    gemm_h<0, false><<<dim3(4, 128), 256, GSM1>>>(valh, (__half*)0, wth + OFF_VQW, (__half*)0,
                                                  vq_b, qvb, (__half*)0, BNQ, DV, DI);
    gemm_h<0, true><<<dim3(4, 128), 256, GSMC>>>(crdh, crdl, wth + OFF_CQW, wtl + OFF_CQW,
                                                 cq_b, qcb, (__half*)0, BNQ, DC, DI);
    rmsnorm_h<<<BNQ, 256>>>(qvb, vq_g, qvh, DI, 1e-6f, 0.125f);
    rmsnorm_h<<<BNQ, 256>>>(qcb, cq_g, qch, DI, 1e-6f, 0.125f);

    // join K branch, attention
    cudaStreamWaitEvent(0, eK, 0);
    attn_h16<<<dim3(NQ/128, NH, BATCH), 256, ATTN_SMEM>>>(qch, qvh, kf, vt, atth);

    // join phase-2 weights, MLP tail
    cudaStreamWaitEvent(0, eW2, 0);
    gemm_h<0, false><<<dim3(4, 128), 256, GSM1>>>(atth, (__half*)0, wth + OFF_OPW, (__half*)0,
                                                  op_b, yb, (__half*)0, BNQ, DI, DV);
    layernorm_t<true><<<BNQ, 256>>>(yb, oln_g, oln_b, ybsh, ybsl, DV, 1e-5f);
    gemm_h<1, false><<<dim3(16, 128), 256, GSM1>>>(ybsh, (__half*)0, wth + OFF_M1W, (__half*)0,
                                                   m1_b, (float*)0, h1h, BNQ, DV, DF);
    gemm_h<1, false><<<dim3(16, 128), 256, GSM1>>>(h1h, (__half*)0, wth + OFF_M2W, (__half*)0,
                                                   m2_b, (float*)0, h2h, BNQ, DF, DF);
    gemm_h<0, false><<<dim3(4, 128), 256, GSM1>>>(h2h, (__half*)0, wth + OFF_M3W, (__half*)0,
                                                  m3_b, out, (__half*)0, BNQ, DF, DV);
}

// round 15
// speedup vs baseline: 1.0087x; 1.0001x over previous
#include <cuda_runtime.h>
#include <cuda_fp16.h>
#include <math.h>
#include <cstdint>

#define BATCH 4
#define NQ 4096
#define NL 1024
#define DV 512
#define DC 128
#define DI 512
#define DF 2048
#define NH 8
#define HD 64

// ---------------- device scratch ----------------
__device__ float g_vk [BATCH * NL * (2 * DI)];
__device__ float g_kc [BATCH * NL * DI];
__device__ float g_qv [BATCH * NQ * DI];
__device__ float g_qc [BATCH * NQ * DI];
__device__ float g_y  [BATCH * NQ * DV];
__device__ __align__(16) __half g_qvh[BATCH * NQ * DI], g_qch[BATCH * NQ * DI];
__device__ __align__(16) __half g_kf [BATCH * NH * NL * 128];
__device__ __align__(16) __half g_vt [BATCH * NH * 64 * NL];
__device__ __align__(16) __half g_sLv_h[BATCH * NL * DV];
__device__ __align__(16) __half g_sLc_h[BATCH * NL * DC], g_sLc_l[BATCH * NL * DC];
__device__ __align__(16) __half g_val_h[BATCH * NQ * DV];
__device__ __align__(16) __half g_crd_h[BATCH * NQ * DC], g_crd_l[BATCH * NQ * DC];
__device__ __align__(16) __half g_att_h[BATCH * NQ * DI];
__device__ __align__(16) __half g_ybs_h[BATCH * NQ * DV], g_ybs_l[BATCH * NQ * DV];
__device__ __align__(16) __half g_h1_h[BATCH * NQ * DF];
__device__ __align__(16) __half g_h2_h[BATCH * NQ * DF];
__device__ __align__(16) __half g_wth[7471104], g_wtl[7471104];

#define OFF_CKW 0
#define OFF_CQW 65536
#define OFF_VQW 131072
#define OFF_VKW 393216
#define OFF_OPW 917504
#define OFF_M1W 1179648
#define OFF_M2W 2228224
#define OFF_M3W 6422528

// ---------------- helpers ----------------
__device__ __forceinline__ float gelu_f(float x) {
    float x3 = x * x * x;
    return 0.5f * x * (1.0f + tanhf(0.7978845608028654f * (x + 0.044715f * x3)));
}
__device__ __forceinline__ void split2h(float x, __half& h, __half& l) {
    h = __float2half_rn(x);
    l = __float2half_rn(x - __half2float(h));
}
__device__ __forceinline__ void mma_f16(float* c, const unsigned* a, unsigned b0, unsigned b1) {
    asm volatile(
        "mma.sync.aligned.m16n8k16.row.col.f32.f16.f16.f32 "
        "{%0,%1,%2,%3},{%4,%5,%6,%7},{%8,%9},{%0,%1,%2,%3};"
        : "+f"(c[0]), "+f"(c[1]), "+f"(c[2]), "+f"(c[3])
        : "r"(a[0]), "r"(a[1]), "r"(a[2]), "r"(a[3]), "r"(b0), "r"(b1));
}
__device__ __forceinline__ void ldsm4(unsigned* r, unsigned addr) {
    asm volatile("ldmatrix.sync.aligned.m8n8.x4.shared.b16 {%0,%1,%2,%3}, [%4];"
        : "=r"(r[0]), "=r"(r[1]), "=r"(r[2]), "=r"(r[3]) : "r"(addr));
}
__device__ __forceinline__ void cpa16(unsigned dst, const void* src) {
    asm volatile("cp.async.cg.shared.global [%0], [%1], 16;" :: "r"(dst), "l"(src));
}
__device__ __forceinline__ void cpa_commit() { asm volatile("cp.async.commit_group;"); }
__device__ __forceinline__ unsigned sh_addr(const void* p) {
    return (unsigned)__cvta_generic_to_shared(p);
}

// ---------------- producers ----------------
__global__ void split_copy_h(const float* __restrict__ x, __half* __restrict__ h,
                             __half* __restrict__ l, int n4) {
    int i = blockIdx.x * blockDim.x + threadIdx.x;
    if (i < n4) {
        float4 v = ((const float4*)x)[i];
        int b = i * 4;
        __half h0, l0; split2h(v.x, h0, l0); h[b] = h0; l[b] = l0;
        split2h(v.y, h0, l0); h[b+1] = h0; l[b+1] = l0;
        split2h(v.z, h0, l0); h[b+2] = h0; l[b+2] = l0;
        split2h(v.w, h0, l0); h[b+3] = h0; l[b+3] = l0;
    }
}

__global__ void convert_h(const float* __restrict__ x, __half* __restrict__ h, int n4) {
    int i = blockIdx.x * blockDim.x + threadIdx.x;
    if (i < n4) {
        float4 v = ((const float4*)x)[i];
        __half2 a, b;
        a.x = __float2half_rn(v.x); a.y = __float2half_rn(v.y);
        b.x = __float2half_rn(v.z); b.y = __float2half_rn(v.w);
        *(__half2*)&h[i * 4]     = a;
        *(__half2*)&h[i * 4 + 2] = b;
    }
}

struct WsArgs {
    const float* W[8];
    __half* th[8];
    __half* tl[8];
    int K[8], N[8];
    int start[9];
};
__global__ void wtsplit_all(WsArgs a) {
    __shared__ float t[32][33];
    int bid = blockIdx.x;
    int l = 0;
    #pragma unroll
    for (int i = 1; i < 8; i++) if (bid >= a.start[i]) l = i;
    int tidx = bid - a.start[l];
    int K = a.K[l], N = a.N[l];
    int ntn = N >> 5;
    int k0 = (tidx / ntn) << 5;
    int n0 = (tidx % ntn) << 5;
    const float* W = a.W[l];
    __half* th = a.th[l];
    __half* tl = a.tl[l];
    int tx = threadIdx.x, ty = threadIdx.y;
    for (int dy = ty; dy < 32; dy += 8)
        t[dy][tx] = W[(size_t)(k0 + dy) * N + n0 + tx];
    __syncthreads();
    for (int rr = ty; rr < 32; rr += 8) {
        __half h, lo; split2h(t[tx][rr], h, lo);
        th[(size_t)(n0 + rr) * K + k0 + tx] = h;
        tl[(size_t)(n0 + rr) * K + k0 + tx] = lo;
    }
}

template <bool SPLIT>
__global__ void layernorm_t(const float* __restrict__ x, const float* __restrict__ g,
                            const float* __restrict__ b, __half* __restrict__ yh,
                            __half* __restrict__ yl, int D, float eps) {
    int row = blockIdx.x;
    const float* xr = x + (size_t)row * D;
    float s = 0.f, ss = 0.f;
    for (int i = threadIdx.x; i < D; i += blockDim.x) { float v = xr[i]; s += v; ss += v * v; }
    __shared__ float rs[32], rss[32];
    #pragma unroll
    for (int off = 16; off; off >>= 1) {
        s  += __shfl_xor_sync(0xffffffffu, s,  off);
        ss += __shfl_xor_sync(0xffffffffu, ss, off);
    }
    int w = threadIdx.x >> 5, l = threadIdx.x & 31;
    if (l == 0) { rs[w] = s; rss[w] = ss; }
    __syncthreads();
    int nw = blockDim.x >> 5;
    if (threadIdx.x < 32) {
        s  = (l < nw) ? rs[l]  : 0.f;
        ss = (l < nw) ? rss[l] : 0.f;
        #pragma unroll
        for (int off = 16; off; off >>= 1) {
            s  += __shfl_xor_sync(0xffffffffu, s,  off);
            ss += __shfl_xor_sync(0xffffffffu, ss, off);
        }
        if (l == 0) { rs[0] = s; rss[0] = ss; }
    }
    __syncthreads();
    float mean = rs[0] / (float)D;
    float inv  = rsqrtf(rss[0] / (float)D - mean * mean + eps);
    for (int i = threadIdx.x; i < D; i += blockDim.x) {
        float v = (xr[i] - mean) * inv * g[i] + b[i];
        if (SPLIT) {
            __half h, lo; split2h(v, h, lo);
            yh[(size_t)row * D + i] = h; yl[(size_t)row * D + i] = lo;
        } else {
            yh[(size_t)row * D + i] = __float2half_rn(v);
        }
    }
}

__global__ void rmsnorm_kernel(float* __restrict__ x, const float* __restrict__ g,
                               int D, float eps, float scale) {
    int row = blockIdx.x;
    float* xr = x + (size_t)row * D;
    float ss = 0.f;
    for (int i = threadIdx.x; i < D; i += blockDim.x) { float v = xr[i]; ss += v * v; }
    __shared__ float rss[32];
    #pragma unroll
    for (int off = 16; off; off >>= 1) ss += __shfl_xor_sync(0xffffffffu, ss, off);
    int w = threadIdx.x >> 5, l = threadIdx.x & 31;
    if (l == 0) rss[w] = ss;
    __syncthreads();
    int nw = blockDim.x >> 5;
    if (threadIdx.x < 32) {
        ss = (l < nw) ? rss[l] : 0.f;
        #pragma unroll
        for (int off = 16; off; off >>= 1) ss += __shfl_xor_sync(0xffffffffu, ss, off);
        if (l == 0) rss[0] = ss;
    }
    __syncthreads();
    float inv = rsqrtf(rss[0] / (float)D + eps) * scale;
    for (int i = threadIdx.x; i < D; i += blockDim.x)
        xr[i] = xr[i] * inv * g[i];
}

__global__ void rmsnorm_h(const float* __restrict__ x, const float* __restrict__ g,
                          __half* __restrict__ y, int D, float eps, float scale) {
    int row = blockIdx.x;
    const float* xr = x + (size_t)row * D;
    float ss = 0.f;
    for (int i = threadIdx.x; i < D; i += blockDim.x) { float v = xr[i]; ss += v * v; }
    __shared__ float rss[32];
    #pragma unroll
    for (int off = 16; off; off >>= 1) ss += __shfl_xor_sync(0xffffffffu, ss, off);
    int w = threadIdx.x >> 5, l = threadIdx.x & 31;
    if (l == 0) rss[w] = ss;
    __syncthreads();
    int nw = blockDim.x >> 5;
    if (threadIdx.x < 32) {
        ss = (l < nw) ? rss[l] : 0.f;
        #pragma unroll
        for (int off = 16; off; off >>= 1) ss += __shfl_xor_sync(0xffffffffu, ss, off);
        if (l == 0) rss[0] = ss;
    }
    __syncthreads();
    float inv = rsqrtf(rss[0] / (float)D + eps) * scale;
    for (int i = threadIdx.x; i < D; i += blockDim.x)
        y[(size_t)row * D + i] = __float2half_rn(xr[i] * inv * g[i]);
}

__global__ void kcomb_kernel(const float* __restrict__ kc, const float* __restrict__ vk,
                             const float* __restrict__ lamp, __half* __restrict__ kf) {
    int j = blockIdx.x, b = blockIdx.y;
    int tid = threadIdx.x;
    float lam = lamp[0];
    int e = tid * 4;
    int h = e >> 7, dd = e & 127;
    float4 v;
    if (dd < 64)
        v = *(const float4*)&kc[((size_t)(b * NL + j)) * DI + h * 64 + dd];
    else {
        v = *(const float4*)&vk[((size_t)(b * NL + j)) * (2 * DI) + DI + h * 64 + (dd - 64)];
        v.x *= lam; v.y *= lam; v.z *= lam; v.w *= lam;
    }
    __half* dst = kf + ((size_t)((b * NH + h) * NL + j)) * 128 + dd;
    dst[0] = __float2half_rn(v.x); dst[1] = __float2half_rn(v.y);
    dst[2] = __float2half_rn(v.z); dst[3] = __float2half_rn(v.w);
}

__global__ void vtrans_kernel(const float* __restrict__ vk, __half* __restrict__ vt) {
    __shared__ float t[32][33];
    int bh = blockIdx.z; int b = bh >> 3; int h = bh & 7;
    int j0 = blockIdx.x * 32, d0 = blockIdx.y * 32;
    int tx = threadIdx.x, ty = threadIdx.y;
    const float* s = vk + ((size_t)(b * NL + j0)) * (2 * DI) + h * HD + d0;
    for (int dy = ty; dy < 32; dy += 8)
        t[dy][tx] = s[(size_t)dy * (2 * DI) + tx];
    __syncthreads();
    for (int dy = ty; dy < 32; dy += 8)
        vt[((size_t)(bh * 64 + d0 + dy)) * NL + j0 + tx] = __float2half_rn(t[tx][dy]);
}

// ---------------- fp16 GEMM 128x128x32, 8 warps (warp tile 32x64) ----------------
// COMP: 2-stage (82KB).  non-COMP: 4-stage (82KB).  Both -> 2 CTA/SM.
#define RSTR 40
#define PLANE_B (128 * RSTR * 2)  // 10240
template <int EPI, bool COMP>    // EPI: 0=bias fp32, 1=bias+gelu fp16
__global__ void __launch_bounds__(256, 2) gemm_h(
    const __half* __restrict__ Ah, const __half* __restrict__ Al,
    const __half* __restrict__ Bh, const __half* __restrict__ Bl,
    const float* __restrict__ bias,
    float* __restrict__ Cf, __half* __restrict__ Chh,
    int M, int K, int N) {
    extern __shared__ char smc[];
    const unsigned smb = sh_addr(smc);
    constexpr int NSTG = COMP ? 2 : 4;
    constexpr unsigned STAGE_B = (COMP ? 4 : 2) * PLANE_B;
    const int tid = threadIdx.x, warp = tid >> 5, lane = tid & 31;
    const int bm = blockIdx.y * 128, bn = blockIdx.x * 128;
    const int wm = (warp & 3) * 32, wn = (warp >> 2) * 64;
    const int g = lane >> 2, tg = lane & 3;
    const int KT = K >> 5;

    float acc[2][8][4];
    #pragma unroll
    for (int i = 0; i < 2; i++)
        #pragma unroll
        for (int j = 0; j < 8; j++)
            #pragma unroll
            for (int k = 0; k < 4; k++) acc[i][j][k] = 0.f;

    auto load_stage = [&](int s, int kt) {
        if (kt < KT) {
            unsigned base = smb + s * STAGE_B;
            #pragma unroll
            for (int i = 0; i < 2; i++) {
                int idx = tid + i * 256;
                int r = idx >> 2, c = idx & 3;
                size_t goA = (size_t)(bm + r) * K + kt * 32 + c * 8;
                size_t goB = (size_t)(bn + r) * K + kt * 32 + c * 8;
                unsigned so = (unsigned)(r * 80 + c * 16);
                cpa16(base + so, Ah + goA);
                cpa16(base + PLANE_B + so, Bh + goB);
                if (COMP) {
                    cpa16(base + 2 * PLANE_B + so, Al + goA);
                    cpa16(base + 3 * PLANE_B + so, Bl + goB);
                }
            }
            cpa_commit();
        }
    };
    load_stage(0, 0);
    if (KT > 1) load_stage(1, 1);
    if (!COMP && KT > 2) load_stage(2, 2);

    const int lrow = lane & 15;
    const int lko = (lane >> 4) * 8;

    for (int kt = 0; kt < KT; kt++) {
        if (COMP) {
            if (kt < KT - 1) asm volatile("cp.async.wait_group 1;" ::: "memory");
            else             asm volatile("cp.async.wait_group 0;" ::: "memory");
        } else {
            if (kt < KT - 2)      asm volatile("cp.async.wait_group 2;" ::: "memory");
            else if (kt < KT - 1) asm volatile("cp.async.wait_group 1;" ::: "memory");
            else                  asm volatile("cp.async.wait_group 0;" ::: "memory");
        }
        __syncthreads();
        int s = kt % NSTG;
        if (!COMP && kt + 3 < KT) load_stage((kt + 3) % 4, kt + 3);
        unsigned aB = smb + s * STAGE_B;
        unsigned bB = aB + PLANE_B;
        #pragma unroll
        for (int ks2 = 0; ks2 < 2; ks2++) {
            int k0 = ks2 * 16;
            unsigned ah[2][4], bh[4][4];
            #pragma unroll
            for (int mt = 0; mt < 2; mt++)
                ldsm4(ah[mt], aB + (unsigned)((wm + mt * 16 + lrow) * RSTR + k0 + lko) * 2);
            #pragma unroll
            for (int nt = 0; nt < 4; nt++)
                ldsm4(bh[nt], bB + (unsigned)((wn + nt * 16 + lrow) * RSTR + k0 + lko) * 2);
            #pragma unroll
            for (int ns = 0; ns < 8; ns++) {
                int nt = ns >> 1, hf = ns & 1;
                unsigned b0 = bh[nt][hf], b1 = bh[nt][hf + 2];
                mma_f16(acc[0][ns], ah[0], b0, b1);
                mma_f16(acc[1][ns], ah[1], b0, b1);
            }
            if (COMP) {
                unsigned al[2][4], bl[4][4];
                #pragma unroll
                for (int mt = 0; mt < 2; mt++)
                    ldsm4(al[mt], aB + 2 * PLANE_B + (unsigned)((wm + mt * 16 + lrow) * RSTR + k0 + lko) * 2);
                #pragma unroll
                for (int nt = 0; nt < 4; nt++)
                    ldsm4(bl[nt], bB + 2 * PLANE_B + (unsigned)((wn + nt * 16 + lrow) * RSTR + k0 + lko) * 2);
                #pragma unroll
                for (int ns = 0; ns < 8; ns++) {
                    int nt = ns >> 1, hf = ns & 1;
                    unsigned bl0 = bl[nt][hf], bl1 = bl[nt][hf + 2];
                    unsigned bh0 = bh[nt][hf], bh1 = bh[nt][hf + 2];
                    mma_f16(acc[0][ns], ah[0], bl0, bl1);
                    mma_f16(acc[1][ns], ah[1], bl0, bl1);
                    mma_f16(acc[0][ns], al[0], bh0, bh1);
                    mma_f16(acc[1][ns], al[1], bh0, bh1);
                }
            }
        }
        __syncthreads();  // convergence barrier (load-bearing, see R6 post-mortem)
        if (COMP && kt + 2 < KT) load_stage(s, kt + 2);
    }

    #pragma unroll
    for (int mf = 0; mf < 2; mf++) {
        int row = bm + wm + mf * 16 + g;
        #pragma unroll
        for (int nf = 0; nf < 8; nf++) {
            int col = bn + wn + nf * 8 + tg * 2;
            float b0v = bias[col], b1v = bias[col + 1];
            float v00 = acc[mf][nf][0] + b0v, v01 = acc[mf][nf][1] + b1v;
            float v10 = acc[mf][nf][2] + b0v, v11 = acc[mf][nf][3] + b1v;
            if (EPI == 1) {
                __half2 p0, p1;
                p0.x = __float2half_rn(gelu_f(v00)); p0.y = __float2half_rn(gelu_f(v01));
                p1.x = __float2half_rn(gelu_f(v10)); p1.y = __float2half_rn(gelu_f(v11));
                *(__half2*)&Chh[(size_t)row * N + col]       = p0;
                *(__half2*)&Chh[(size_t)(row + 8) * N + col] = p1;
            } else {
                *(float2*)&Cf[(size_t)row * N + col]       = make_float2(v00, v01);
                *(float2*)&Cf[(size_t)(row + 8) * N + col] = make_float2(v10, v11);
            }
        }
    }
}

// ---------------- fp16 dual-score flash attention (Q frags hoisted to regs) ----------------
#define QS2 136
#define VS2 72
#define PS2 72
__global__ void __launch_bounds__(256) attn_h16(const __half* __restrict__ Qc,
                                                const __half* __restrict__ Qv,
                                                const __half* __restrict__ Kf,
                                                const __half* __restrict__ Vt,
                                                __half* __restrict__ outh) {
    extern __shared__ char smc[];
    const unsigned smb = sh_addr(smc);
    const unsigned qsb = smb;
    const unsigned ksb = qsb + 128 * QS2 * 2;
    const unsigned vsb = ksb + 2 * 64 * QS2 * 2;
    const unsigned psb = vsb + 2 * 64 * VS2 * 2;
    const int tid = threadIdx.x, warp = tid >> 5, lane = tid & 31;
    const int g = lane >> 2, tg = lane & 3;
    const int q0 = blockIdx.x * 128, h = blockIdx.y, b = blockIdx.z;
    const int bh = b * NH + h;

    const __half* qcb_ = Qc + ((size_t)(b * NQ + q0)) * DI + h * HD;
    const __half* qvb_ = Qv + ((size_t)(b * NQ + q0)) * DI + h * HD;
    #pragma unroll
    for (int i = 0; i < 8; i++) {
        int idx = tid + i * 256;
        int r = idx >> 4, c = idx & 15;
        const __half* src = (c < 8) ? (qcb_ + (size_t)r * DI + c * 8)
                                    : (qvb_ + (size_t)r * DI + (c - 8) * 8);
        cpa16(qsb + (unsigned)(r * QS2 + c * 8) * 2, src);
    }
    cpa_commit();

    const __half* kfb = Kf + (size_t)bh * NL * 128;
    const __half* vtb = Vt + (size_t)bh * 64 * NL;
    auto load_kv = [&](int s, int m0) {
        unsigned ks_ = ksb + s * (64 * QS2 * 2);
        unsigned vs_ = vsb + s * (64 * VS2 * 2);
        #pragma unroll
        for (int i = 0; i < 4; i++) {
            int idx = tid + i * 256;
            int r = idx >> 4, c = idx & 15;
            cpa16(ks_ + (unsigned)(r * QS2 + c * 8) * 2, kfb + (size_t)(m0 + r) * 128 + c * 8);
        }
        #pragma unroll
        for (int i = 0; i < 2; i++) {
            int idx = tid + i * 256;
            int r = idx >> 3, c = idx & 7;
            cpa16(vs_ + (unsigned)(r * VS2 + c * 8) * 2, vtb + (size_t)r * NL + m0 + c * 8);
        }
        cpa_commit();
    };
    load_kv(0, 0);
    load_kv(1, 64);

    const int wrow = warp * 16;
    const int lrow = lane & 15;
    const int lko = (lane >> 4) * 8;

    // hoist Q fragments into registers: Q group complete once <=2 groups pending
    asm volatile("cp.async.wait_group 2;" ::: "memory");
    __syncthreads();
    unsigned aq[8][4];
    #pragma unroll
    for (int kc2 = 0; kc2 < 8; kc2++)
        ldsm4(aq[kc2], qsb + (unsigned)((wrow + lrow) * QS2 + kc2 * 16 + lko) * 2);

    float m_[2] = {-1e30f, -1e30f}, l_[2] = {0.f, 0.f};
    float o[8][4];
    #pragma unroll
    for (int i = 0; i < 8; i++)
        #pragma unroll
        for (int j = 0; j < 4; j++) o[i][j] = 0.f;

    const int NIT = NL / 64;

    for (int it = 0; it < NIT; it++) {
        if (it < NIT - 1) asm volatile("cp.async.wait_group 1;" ::: "memory");
        else              asm volatile("cp.async.wait_group 0;" ::: "memory");
        __syncthreads();
        int s = it & 1;
        unsigned ksp = ksb + s * (64 * QS2 * 2);
        unsigned vsp = vsb + s * (64 * VS2 * 2);

        float sacc[8][4];
        #pragma unroll
        for (int i = 0; i < 8; i++)
            #pragma unroll
            for (int j = 0; j < 4; j++) sacc[i][j] = 0.f;
        #pragma unroll
        for (int kc2 = 0; kc2 < 8; kc2++) {
            int k0 = kc2 * 16;
            unsigned bh4[4][4];
            #pragma unroll
            for (int nt = 0; nt < 4; nt++)
                ldsm4(bh4[nt], ksp + (unsigned)((nt * 16 + lrow) * QS2 + k0 + lko) * 2);
            #pragma unroll
            for (int ns = 0; ns < 8; ns++) {
                int nt = ns >> 1, hf = ns & 1;
                mma_f16(sacc[ns], aq[kc2], bh4[nt][hf], bh4[nt][hf + 2]);
            }
        }

        #pragma unroll
        for (int rw = 0; rw < 2; rw++) {
            float mx = -1e30f;
            #pragma unroll
            for (int nf = 0; nf < 8; nf++)
                mx = fmaxf(mx, fmaxf(sacc[nf][2 * rw], sacc[nf][2 * rw + 1]));
            mx = fmaxf(mx, __shfl_xor_sync(0xffffffffu, mx, 1));
            mx = fmaxf(mx, __shfl_xor_sync(0xffffffffu, mx, 2));
            float mn = fmaxf(m_[rw], mx);
            float corr = __expf(m_[rw] - mn);
            m_[rw] = mn;
            float sum = 0.f;
            int prow = wrow + rw * 8 + g;
            #pragma unroll
            for (int nf = 0; nf < 8; nf++) {
                float p0 = __expf(sacc[nf][2 * rw] - mn);
                float p1 = __expf(sacc[nf][2 * rw + 1] - mn);
                sum += p0 + p1;
                __half2 ph; ph.x = __float2half_rn(p0); ph.y = __float2half_rn(p1);
                unsigned pa = psb + (unsigned)(prow * PS2 + nf * 8 + tg * 2) * 2;
                asm volatile("st.shared.b32 [%0], %1;" :: "r"(pa), "r"(*(unsigned*)&ph));
            }
            sum += __shfl_xor_sync(0xffffffffu, sum, 1);
            sum += __shfl_xor_sync(0xffffffffu, sum, 2);
            l_[rw] = l_[rw] * corr + sum;
            #pragma unroll
            for (int nf = 0; nf < 8; nf++) {
                o[nf][2 * rw]     *= corr;
                o[nf][2 * rw + 1] *= corr;
            }
        }
        __syncwarp();

        #pragma unroll
        for (int kc2 = 0; kc2 < 4; kc2++) {
            int k0 = kc2 * 16;
            unsigned a[4], bv[4][4];
            ldsm4(a, psb + (unsigned)((wrow + lrow) * PS2 + k0 + lko) * 2);
            #pragma unroll
            for (int nt = 0; nt < 4; nt++)
                ldsm4(bv[nt], vsp + (unsigned)((nt * 16 + lrow) * VS2 + k0 + lko) * 2);
            #pragma unroll
            for (int ns = 0; ns < 8; ns++) {
                int nt = ns >> 1, hf = ns & 1;
                mma_f16(o[ns], a, bv[nt][hf], bv[nt][hf + 2]);
            }
        }
        __syncthreads();
        if (it + 2 < NIT) load_kv(s, (it + 2) * 64);
    }

    #pragma unroll
    for (int rw = 0; rw < 2; rw++) {
        float inv = 1.f / l_[rw];
        int row = b * NQ + q0 + wrow + rw * 8 + g;
        #pragma unroll
        for (int nf = 0; nf < 8; nf++) {
            int col = h * HD + nf * 8 + tg * 2;
            __half2 hv;
            hv.x = __float2half_rn(o[nf][2 * rw] * inv);
            hv.y = __float2half_rn(o[nf][2 * rw + 1] * inv);
            *(__half2*)&outh[(size_t)row * DI + col] = hv;
        }
    }
}

// ---------------- host launcher ----------------
static void fill_ws(WsArgs& wa, const float** Ws, __half* wth, __half* wtl,
                    const int* Ks, const int* Ns, const int* offs, int n, int& total) {
    int acc0 = 0;
    for (int i = 0; i < n; i++) {
        wa.W[i] = Ws[i]; wa.th[i] = wth + offs[i]; wa.tl[i] = wtl + offs[i];
        wa.K[i] = Ks[i]; wa.N[i] = Ns[i];
        wa.start[i] = acc0;
        acc0 += (Ks[i] / 32) * (Ns[i] / 32);
    }
    for (int i = n; i < 9; i++) wa.start[i] = 0x7FFFFFFF;
    total = acc0;
}

extern "C" void kernel_launch(void* const* d_in, const int* in_sizes, int n_in,
                              void* d_out, int out_size) {
    const float* coords = (const float*)d_in[0];
    const float* values = (const float*)d_in[1];
    const float* Lv     = (const float*)d_in[2];
    const float* Lc     = (const float*)d_in[3];
    const float* lam    = (const float*)d_in[4];
    const float* lvn_g  = (const float*)d_in[5];
    const float* lvn_b  = (const float*)d_in[6];
    const float* lcn_g  = (const float*)d_in[7];
    const float* lcn_b  = (const float*)d_in[8];
    const float* ck_w   = (const float*)d_in[9];
    const float* ck_b   = (const float*)d_in[10];
    const float* ck_g   = (const float*)d_in[11];
    const float* cq_w   = (const float*)d_in[12];
    const float* cq_b   = (const float*)d_in[13];
    const float* cq_g   = (const float*)d_in[14];
    const float* vq_w   = (const float*)d_in[15];
    const float* vq_b   = (const float*)d_in[16];
    const float* vq_g   = (const float*)d_in[17];
    const float* vk_w   = (const float*)d_in[18];
    const float* vk_b   = (const float*)d_in[19];
    const float* op_w   = (const float*)d_in[20];
    const float* op_b   = (const float*)d_in[21];
    const float* oln_g  = (const float*)d_in[22];
    const float* oln_b  = (const float*)d_in[23];
    const float* m1_w   = (const float*)d_in[24];
    const float* m1_b   = (const float*)d_in[25];
    const float* m2_w   = (const float*)d_in[26];
    const float* m2_b   = (const float*)d_in[27];
    const float* m3_w   = (const float*)d_in[28];
    const float* m3_b   = (const float*)d_in[29];
    float* out = (float*)d_out;

    float *vkb, *kcb, *qvb, *qcb, *yb;
    cudaGetSymbolAddress((void**)&vkb, g_vk);
    cudaGetSymbolAddress((void**)&kcb, g_kc);
    cudaGetSymbolAddress((void**)&qvb, g_qv);
    cudaGetSymbolAddress((void**)&qcb, g_qc);
    cudaGetSymbolAddress((void**)&yb,  g_y);
    __half *sLvh, *sLch, *sLcl, *valh, *crdh, *crdl;
    __half *atth, *ybsh, *ybsl, *h1h, *h2h, *wth, *wtl;
    __half *qvh, *qch, *kf, *vt;
    cudaGetSymbolAddress((void**)&sLvh, g_sLv_h);
    cudaGetSymbolAddress((void**)&sLch, g_sLc_h); cudaGetSymbolAddress((void**)&sLcl, g_sLc_l);
    cudaGetSymbolAddress((void**)&valh, g_val_h);
    cudaGetSymbolAddress((void**)&crdh, g_crd_h); cudaGetSymbolAddress((void**)&crdl, g_crd_l);
    cudaGetSymbolAddress((void**)&atth, g_att_h);
    cudaGetSymbolAddress((void**)&ybsh, g_ybs_h); cudaGetSymbolAddress((void**)&ybsl, g_ybs_l);
    cudaGetSymbolAddress((void**)&h1h,  g_h1_h);
    cudaGetSymbolAddress((void**)&h2h,  g_h2_h);
    cudaGetSymbolAddress((void**)&wth,  g_wth);   cudaGetSymbolAddress((void**)&wtl,  g_wtl);
    cudaGetSymbolAddress((void**)&qvh,  g_qvh);   cudaGetSymbolAddress((void**)&qch,  g_qch);
    cudaGetSymbolAddress((void**)&kf,   g_kf);    cudaGetSymbolAddress((void**)&vt,   g_vt);

    const int BNL = BATCH * NL;
    const int BNQ = BATCH * NQ;
    const int GSMC = 2 * 4 * PLANE_B;  // 81920 (compensated, 2-stage)
    const int GSM1 = 4 * 2 * PLANE_B;  // 81920 (single-pass, 4-stage)
    const int ATTN_SMEM = 128 * QS2 * 2 + 2 * 64 * QS2 * 2 + 2 * 64 * VS2 * 2 + 128 * PS2 * 2;
    cudaFuncSetAttribute((const void*)gemm_h<0, true>,  cudaFuncAttributeMaxDynamicSharedMemorySize, GSMC);
    cudaFuncSetAttribute((const void*)gemm_h<0, false>, cudaFuncAttributeMaxDynamicSharedMemorySize, GSM1);
    cudaFuncSetAttribute((const void*)gemm_h<1, false>, cudaFuncAttributeMaxDynamicSharedMemorySize, GSM1);
    cudaFuncSetAttribute(attn_h16, cudaFuncAttributeMaxDynamicSharedMemorySize, ATTN_SMEM);

    cudaStream_t s1;
    cudaStreamCreateWithFlags(&s1, cudaStreamNonBlocking);
    cudaEvent_t eF, eW, eK, eW2;
    cudaEventCreateWithFlags(&eF,  cudaEventDisableTiming);
    cudaEventCreateWithFlags(&eW,  cudaEventDisableTiming);
    cudaEventCreateWithFlags(&eK,  cudaEventDisableTiming);
    cudaEventCreateWithFlags(&eW2, cudaEventDisableTiming);

    // fork: latent/K branch starts immediately
    cudaEventRecord(eF, 0);
    cudaStreamWaitEvent(s1, eF, 0);
    layernorm_t<false><<<BNL, 256, 0, s1>>>(Lv, lvn_g, lvn_b, sLvh, (__half*)0, DV, 1e-5f);
    layernorm_t<true><<<BNL, 128, 0, s1>>>(Lc, lcn_g, lcn_b, sLch, sLcl, DC, 1e-5f);

    // weight split PHASE 1 on main: projection weights
    {
        WsArgs wa; int tot;
        const float* Ws[4] = {ck_w, cq_w, vq_w, vk_w};
        int Ks[4] = {DC, DC, DV, DV};
        int Ns[4] = {DI, DI, DI, 2 * DI};
        int offs[4] = {OFF_CKW, OFF_CQW, OFF_VQW, OFF_VKW};
        fill_ws(wa, Ws, wth, wtl, Ks, Ns, offs, 4, tot);
        wtsplit_all<<<tot, dim3(32, 8)>>>(wa);
    }
    cudaEventRecord(eW, 0);

    // latent/K branch on s1
    cudaStreamWaitEvent(s1, eW, 0);
    gemm_h<0, false><<<dim3(8, 32), 256, GSM1, s1>>>(sLvh, (__half*)0, wth + OFF_VKW, (__half*)0,
                                                     vk_b, vkb, (__half*)0, BNL, DV, 2 * DI);
    gemm_h<0, true><<<dim3(4, 32), 256, GSMC, s1>>>(sLch, sLcl, wth + OFF_CKW, wtl + OFF_CKW,
                                                    ck_b, kcb, (__half*)0, BNL, DC, DI);
    rmsnorm_kernel<<<BNL, 256, 0, s1>>>(kcb, ck_g, DI, 1e-6f, 1.0f);
    kcomb_kernel<<<dim3(NL, BATCH), 256, 0, s1>>>(kcb, vkb, lam, kf);
    vtrans_kernel<<<dim3(NL/32, 2, BATCH*NH), dim3(32, 8), 0, s1>>>(vkb, vt);
    cudaEventRecord(eK, s1);

    // weight split PHASE 2 on s1 — overlaps attention on main
    {
        WsArgs wa; int tot;
        const float* Ws[4] = {op_w, m1_w, m2_w, m3_w};
        int Ks[4] = {DI, DV, DF, DF};
        int Ns[4] = {DV, DF, DF, DV};
        int offs[4] = {OFF_OPW, OFF_M1W, OFF_M2W, OFF_M3W};
        fill_ws(wa, Ws, wth, wtl, Ks, Ns, offs, 4, tot);
        wtsplit_all<<<tot, dim3(32, 8), 0, s1>>>(wa);
    }
    cudaEventRecord(eW2, s1);

    // q branch on main stream
    convert_h<<<BNQ * DV / 4 / 256, 256>>>(values, valh, BNQ * DV / 4);
    split_copy_h<<<BNQ * DC / 4 / 256, 256>>>(coords, crdh, crdl, BNQ * DC / 4);
    gemm_h<0, false><<<dim3(4, 128), 256, GSM1>>>(valh, (__half*)0, wth + OFF_VQW, (__half*)0,
                                                  vq_b, qvb, (__half*)0, BNQ, DV, DI);
    gemm_h<0, true><<<dim3(4, 128), 256, GSMC>>>(crdh, crdl, wth + OFF_CQW, wtl + OFF_CQW,
                                                 cq_b, qcb, (__half*)0, BNQ, DC, DI);
    rmsnorm_h<<<BNQ, 256>>>(qvb, vq_g, qvh, DI, 1e-6f, 0.125f);
    rmsnorm_h<<<BNQ, 256>>>(qcb, cq_g, qch, DI, 1e-6f, 0.125f);

    // join K branch, attention
    cudaStreamWaitEvent(0, eK, 0);
    attn_h16<<<dim3(NQ/128, NH, BATCH), 256, ATTN_SMEM>>>(qch, qvh, kf, vt, atth);

    // join phase-2 weights, MLP tail
    cudaStreamWaitEvent(0, eW2, 0);
    gemm_h<0, false><<<dim3(4, 128), 256, GSM1>>>(atth, (__half*)0, wth + OFF_OPW, (__half*)0,
                                                  op_b, yb, (__half*)0, BNQ, DI, DV);
    layernorm_t<true><<<BNQ, 256>>>(yb, oln_g, oln_b, ybsh, ybsl, DV, 1e-5f);
    gemm_h<1, false><<<dim3(16, 128), 256, GSM1>>>(ybsh, (__half*)0, wth + OFF_M1W, (__half*)0,
                                                   m1_b, (float*)0, h1h, BNQ, DV, DF);
    gemm_h<1, false><<<dim3(16, 128), 256, GSM1>>>(h1h, (__half*)0, wth + OFF_M2W, (__half*)0,
                                                   m2_b, (float*)0, h2h, BNQ, DF, DF);
    gemm_h<0, false><<<dim3(4, 128), 256, GSM1>>>(h2h, (__half*)0, wth + OFF_M3W, (__half*)0,
                                                  m3_b, out, (__half*)0, BNQ, DF, DV);
}

// round 17
// speedup vs baseline: 1.0221x; 1.0133x over previous
#include <cuda_runtime.h>
#include <cuda_fp16.h>
#include <math.h>
#include <cstdint>

#define BATCH 4
#define NQ 4096
#define NL 1024
#define DV 512
#define DC 128
#define DI 512
#define DF 2048
#define NH 8
#define HD 64

// ---------------- device scratch ----------------
__device__ float g_vk [BATCH * NL * (2 * DI)];
__device__ float g_kc [BATCH * NL * DI];
__device__ float g_qv [BATCH * NQ * DI];
__device__ float g_qc [BATCH * NQ * DI];
__device__ float g_y  [BATCH * NQ * DV];
__device__ __align__(16) __half g_qvh[BATCH * NQ * DI], g_qch[BATCH * NQ * DI];
__device__ __align__(16) __half g_kf [BATCH * NH * NL * 128];
__device__ __align__(16) __half g_vt [BATCH * NH * 64 * NL];
__device__ __align__(16) __half g_sLv_h[BATCH * NL * DV];
__device__ __align__(16) __half g_sLc_h[BATCH * NL * DC], g_sLc_l[BATCH * NL * DC];
__device__ __align__(16) __half g_val_h[BATCH * NQ * DV];
__device__ __align__(16) __half g_crd_h[BATCH * NQ * DC], g_crd_l[BATCH * NQ * DC];
__device__ __align__(16) __half g_att_h[BATCH * NQ * DI];
__device__ __align__(16) __half g_ybs_h[BATCH * NQ * DV], g_ybs_l[BATCH * NQ * DV];
__device__ __align__(16) __half g_h1_h[BATCH * NQ * DF];
__device__ __align__(16) __half g_h2_h[BATCH * NQ * DF];
__device__ __align__(16) __half g_wth[7471104], g_wtl[7471104];

#define OFF_CKW 0
#define OFF_CQW 65536
#define OFF_VQW 131072
#define OFF_VKW 393216
#define OFF_OPW 917504
#define OFF_M1W 1179648
#define OFF_M2W 2228224
#define OFF_M3W 6422528

// ---------------- helpers ----------------
__device__ __forceinline__ float gelu_f(float x) {
    float x3 = x * x * x;
    return 0.5f * x * (1.0f + tanhf(0.7978845608028654f * (x + 0.044715f * x3)));
}
__device__ __forceinline__ void split2h(float x, __half& h, __half& l) {
    h = __float2half_rn(x);
    l = __float2half_rn(x - __half2float(h));
}
__device__ __forceinline__ void mma_f16(float* c, const unsigned* a, unsigned b0, unsigned b1) {
    asm volatile(
        "mma.sync.aligned.m16n8k16.row.col.f32.f16.f16.f32 "
        "{%0,%1,%2,%3},{%4,%5,%6,%7},{%8,%9},{%0,%1,%2,%3};"
        : "+f"(c[0]), "+f"(c[1]), "+f"(c[2]), "+f"(c[3])
        : "r"(a[0]), "r"(a[1]), "r"(a[2]), "r"(a[3]), "r"(b0), "r"(b1));
}
__device__ __forceinline__ void ldsm4(unsigned* r, unsigned addr) {
    asm volatile("ldmatrix.sync.aligned.m8n8.x4.shared.b16 {%0,%1,%2,%3}, [%4];"
        : "=r"(r[0]), "=r"(r[1]), "=r"(r[2]), "=r"(r[3]) : "r"(addr));
}
__device__ __forceinline__ void cpa16(unsigned dst, const void* src) {
    asm volatile("cp.async.cg.shared.global [%0], [%1], 16;" :: "r"(dst), "l"(src));
}
__device__ __forceinline__ void cpa_commit() { asm volatile("cp.async.commit_group;"); }
__device__ __forceinline__ unsigned sh_addr(const void* p) {
    return (unsigned)__cvta_generic_to_shared(p);
}
__device__ __forceinline__ unsigned pack_h2(float a, float b) {
    __half2 h; h.x = __float2half_rn(a); h.y = __float2half_rn(b);
    return *(unsigned*)&h;
}

// ---------------- producers ----------------
__global__ void split_copy_h(const float* __restrict__ x, __half* __restrict__ h,
                             __half* __restrict__ l, int n4) {
    int i = blockIdx.x * blockDim.x + threadIdx.x;
    if (i < n4) {
        float4 v = ((const float4*)x)[i];
        int b = i * 4;
        __half h0, l0; split2h(v.x, h0, l0); h[b] = h0; l[b] = l0;
        split2h(v.y, h0, l0); h[b+1] = h0; l[b+1] = l0;
        split2h(v.z, h0, l0); h[b+2] = h0; l[b+2] = l0;
        split2h(v.w, h0, l0); h[b+3] = h0; l[b+3] = l0;
    }
}

__global__ void convert_h(const float* __restrict__ x, __half* __restrict__ h, int n4) {
    int i = blockIdx.x * blockDim.x + threadIdx.x;
    if (i < n4) {
        float4 v = ((const float4*)x)[i];
        __half2 a, b;
        a.x = __float2half_rn(v.x); a.y = __float2half_rn(v.y);
        b.x = __float2half_rn(v.z); b.y = __float2half_rn(v.w);
        *(__half2*)&h[i * 4]     = a;
        *(__half2*)&h[i * 4 + 2] = b;
    }
}

struct WsArgs {
    const float* W[8];
    __half* th[8];
    __half* tl[8];
    int K[8], N[8];
    int start[9];
};
__global__ void wtsplit_all(WsArgs a) {
    __shared__ float t[32][33];
    int bid = blockIdx.x;
    int l = 0;
    #pragma unroll
    for (int i = 1; i < 8; i++) if (bid >= a.start[i]) l = i;
    int tidx = bid - a.start[l];
    int K = a.K[l], N = a.N[l];
    int ntn = N >> 5;
    int k0 = (tidx / ntn) << 5;
    int n0 = (tidx % ntn) << 5;
    const float* W = a.W[l];
    __half* th = a.th[l];
    __half* tl = a.tl[l];
    int tx = threadIdx.x, ty = threadIdx.y;
    for (int dy = ty; dy < 32; dy += 8)
        t[dy][tx] = W[(size_t)(k0 + dy) * N + n0 + tx];
    __syncthreads();
    for (int rr = ty; rr < 32; rr += 8) {
        __half h, lo; split2h(t[tx][rr], h, lo);
        th[(size_t)(n0 + rr) * K + k0 + tx] = h;
        tl[(size_t)(n0 + rr) * K + k0 + tx] = lo;
    }
}

template <bool SPLIT>
__global__ void layernorm_t(const float* __restrict__ x, const float* __restrict__ g,
                            const float* __restrict__ b, __half* __restrict__ yh,
                            __half* __restrict__ yl, int D, float eps) {
    int row = blockIdx.x;
    const float* xr = x + (size_t)row * D;
    float s = 0.f, ss = 0.f;
    for (int i = threadIdx.x; i < D; i += blockDim.x) { float v = xr[i]; s += v; ss += v * v; }
    __shared__ float rs[32], rss[32];
    #pragma unroll
    for (int off = 16; off; off >>= 1) {
        s  += __shfl_xor_sync(0xffffffffu, s,  off);
        ss += __shfl_xor_sync(0xffffffffu, ss, off);
    }
    int w = threadIdx.x >> 5, l = threadIdx.x & 31;
    if (l == 0) { rs[w] = s; rss[w] = ss; }
    __syncthreads();
    int nw = blockDim.x >> 5;
    if (threadIdx.x < 32) {
        s  = (l < nw) ? rs[l]  : 0.f;
        ss = (l < nw) ? rss[l] : 0.f;
        #pragma unroll
        for (int off = 16; off; off >>= 1) {
            s  += __shfl_xor_sync(0xffffffffu, s,  off);
            ss += __shfl_xor_sync(0xffffffffu, ss, off);
        }
        if (l == 0) { rs[0] = s; rss[0] = ss; }
    }
    __syncthreads();
    float mean = rs[0] / (float)D;
    float inv  = rsqrtf(rss[0] / (float)D - mean * mean + eps);
    for (int i = threadIdx.x; i < D; i += blockDim.x) {
        float v = (xr[i] - mean) * inv * g[i] + b[i];
        if (SPLIT) {
            __half h, lo; split2h(v, h, lo);
            yh[(size_t)row * D + i] = h; yl[(size_t)row * D + i] = lo;
        } else {
            yh[(size_t)row * D + i] = __float2half_rn(v);
        }
    }
}

__global__ void rmsnorm_kernel(float* __restrict__ x, const float* __restrict__ g,
                               int D, float eps, float scale) {
    int row = blockIdx.x;
    float* xr = x + (size_t)row * D;
    float ss = 0.f;
    for (int i = threadIdx.x; i < D; i += blockDim.x) { float v = xr[i]; ss += v * v; }
    __shared__ float rss[32];
    #pragma unroll
    for (int off = 16; off; off >>= 1) ss += __shfl_xor_sync(0xffffffffu, ss, off);
    int w = threadIdx.x >> 5, l = threadIdx.x & 31;
    if (l == 0) rss[w] = ss;
    __syncthreads();
    int nw = blockDim.x >> 5;
    if (threadIdx.x < 32) {
        ss = (l < nw) ? rss[l] : 0.f;
        #pragma unroll
        for (int off = 16; off; off >>= 1) ss += __shfl_xor_sync(0xffffffffu, ss, off);
        if (l == 0) rss[0] = ss;
    }
    __syncthreads();
    float inv = rsqrtf(rss[0] / (float)D + eps) * scale;
    for (int i = threadIdx.x; i < D; i += blockDim.x)
        xr[i] = xr[i] * inv * g[i];
}

__global__ void rmsnorm_h(const float* __restrict__ x, const float* __restrict__ g,
                          __half* __restrict__ y, int D, float eps, float scale) {
    int row = blockIdx.x;
    const float* xr = x + (size_t)row * D;
    float ss = 0.f;
    for (int i = threadIdx.x; i < D; i += blockDim.x) { float v = xr[i]; ss += v * v; }
    __shared__ float rss[32];
    #pragma unroll
    for (int off = 16; off; off >>= 1) ss += __shfl_xor_sync(0xffffffffu, ss, off);
    int w = threadIdx.x >> 5, l = threadIdx.x & 31;
    if (l == 0) rss[w] = ss;
    __syncthreads();
    int nw = blockDim.x >> 5;
    if (threadIdx.x < 32) {
        ss = (l < nw) ? rss[l] : 0.f;
        #pragma unroll
        for (int off = 16; off; off >>= 1) ss += __shfl_xor_sync(0xffffffffu, ss, off);
        if (l == 0) rss[0] = ss;
    }
    __syncthreads();
    float inv = rsqrtf(rss[0] / (float)D + eps) * scale;
    for (int i = threadIdx.x; i < D; i += blockDim.x)
        y[(size_t)row * D + i] = __float2half_rn(xr[i] * inv * g[i]);
}

__global__ void kcomb_kernel(const float* __restrict__ kc, const float* __restrict__ vk,
                             const float* __restrict__ lamp, __half* __restrict__ kf) {
    int j = blockIdx.x, b = blockIdx.y;
    int tid = threadIdx.x;
    float lam = lamp[0];
    int e = tid * 4;
    int h = e >> 7, dd = e & 127;
    float4 v;
    if (dd < 64)
        v = *(const float4*)&kc[((size_t)(b * NL + j)) * DI + h * 64 + dd];
    else {
        v = *(const float4*)&vk[((size_t)(b * NL + j)) * (2 * DI) + DI + h * 64 + (dd - 64)];
        v.x *= lam; v.y *= lam; v.z *= lam; v.w *= lam;
    }
    __half* dst = kf + ((size_t)((b * NH + h) * NL + j)) * 128 + dd;
    dst[0] = __float2half_rn(v.x); dst[1] = __float2half_rn(v.y);
    dst[2] = __float2half_rn(v.z); dst[3] = __float2half_rn(v.w);
}

__global__ void vtrans_kernel(const float* __restrict__ vk, __half* __restrict__ vt) {
    __shared__ float t[32][33];
    int bh = blockIdx.z; int b = bh >> 3; int h = bh & 7;
    int j0 = blockIdx.x * 32, d0 = blockIdx.y * 32;
    int tx = threadIdx.x, ty = threadIdx.y;
    const float* s = vk + ((size_t)(b * NL + j0)) * (2 * DI) + h * HD + d0;
    for (int dy = ty; dy < 32; dy += 8)
        t[dy][tx] = s[(size_t)dy * (2 * DI) + tx];
    __syncthreads();
    for (int dy = ty; dy < 32; dy += 8)
        vt[((size_t)(bh * 64 + d0 + dy)) * NL + j0 + tx] = __float2half_rn(t[tx][dy]);
}

// ---------------- fp16 GEMM 128x128x32, 8 warps (warp tile 32x64) ----------------
#define RSTR 40
#define PLANE_B (128 * RSTR * 2)  // 10240
template <int EPI, bool COMP>    // EPI: 0=bias fp32, 1=bias+gelu fp16
__global__ void __launch_bounds__(256, 2) gemm_h(
    const __half* __restrict__ Ah, const __half* __restrict__ Al,
    const __half* __restrict__ Bh, const __half* __restrict__ Bl,
    const float* __restrict__ bias,
    float* __restrict__ Cf, __half* __restrict__ Chh,
    int M, int K, int N) {
    extern __shared__ char smc[];
    const unsigned smb = sh_addr(smc);
    constexpr int NSTG = COMP ? 2 : 4;
    constexpr unsigned STAGE_B = (COMP ? 4 : 2) * PLANE_B;
    const int tid = threadIdx.x, warp = tid >> 5, lane = tid & 31;
    const int bm = blockIdx.y * 128, bn = blockIdx.x * 128;
    const int wm = (warp & 3) * 32, wn = (warp >> 2) * 64;
    const int g = lane >> 2, tg = lane & 3;
    const int KT = K >> 5;

    float acc[2][8][4];
    #pragma unroll
    for (int i = 0; i < 2; i++)
        #pragma unroll
        for (int j = 0; j < 8; j++)
            #pragma unroll
            for (int k = 0; k < 4; k++) acc[i][j][k] = 0.f;

    auto load_stage = [&](int s, int kt) {
        if (kt < KT) {
            unsigned base = smb + s * STAGE_B;
            #pragma unroll
            for (int i = 0; i < 2; i++) {
                int idx = tid + i * 256;
                int r = idx >> 2, c = idx & 3;
                size_t goA = (size_t)(bm + r) * K + kt * 32 + c * 8;
                size_t goB = (size_t)(bn + r) * K + kt * 32 + c * 8;
                unsigned so = (unsigned)(r * 80 + c * 16);
                cpa16(base + so, Ah + goA);
                cpa16(base + PLANE_B + so, Bh + goB);
                if (COMP) {
                    cpa16(base + 2 * PLANE_B + so, Al + goA);
                    cpa16(base + 3 * PLANE_B + so, Bl + goB);
                }
            }
            cpa_commit();
        }
    };
    load_stage(0, 0);
    if (KT > 1) load_stage(1, 1);
    if (!COMP && KT > 2) load_stage(2, 2);

    const int lrow = lane & 15;
    const int lko = (lane >> 4) * 8;

    for (int kt = 0; kt < KT; kt++) {
        if (COMP) {
            if (kt < KT - 1) asm volatile("cp.async.wait_group 1;" ::: "memory");
            else             asm volatile("cp.async.wait_group 0;" ::: "memory");
        } else {
            if (kt < KT - 2)      asm volatile("cp.async.wait_group 2;" ::: "memory");
            else if (kt < KT - 1) asm volatile("cp.async.wait_group 1;" ::: "memory");
            else                  asm volatile("cp.async.wait_group 0;" ::: "memory");
        }
        __syncthreads();
        int s = kt % NSTG;
        if (!COMP && kt + 3 < KT) load_stage((kt + 3) % 4, kt + 3);
        unsigned aB = smb + s * STAGE_B;
        unsigned bB = aB + PLANE_B;
        #pragma unroll
        for (int ks2 = 0; ks2 < 2; ks2++) {
            int k0 = ks2 * 16;
            unsigned ah[2][4], bh[4][4];
            #pragma unroll
            for (int mt = 0; mt < 2; mt++)
                ldsm4(ah[mt], aB + (unsigned)((wm + mt * 16 + lrow) * RSTR + k0 + lko) * 2);
            #pragma unroll
            for (int nt = 0; nt < 4; nt++)
                ldsm4(bh[nt], bB + (unsigned)((wn + nt * 16 + lrow) * RSTR + k0 + lko) * 2);
            #pragma unroll
            for (int ns = 0; ns < 8; ns++) {
                int nt = ns >> 1, hf = ns & 1;
                unsigned b0 = bh[nt][hf], b1 = bh[nt][hf + 2];
                mma_f16(acc[0][ns], ah[0], b0, b1);
                mma_f16(acc[1][ns], ah[1], b0, b1);
            }
            if (COMP) {
                unsigned al[2][4], bl[4][4];
                #pragma unroll
                for (int mt = 0; mt < 2; mt++)
                    ldsm4(al[mt], aB + 2 * PLANE_B + (unsigned)((wm + mt * 16 + lrow) * RSTR + k0 + lko) * 2);
                #pragma unroll
                for (int nt = 0; nt < 4; nt++)
                    ldsm4(bl[nt], bB + 2 * PLANE_B + (unsigned)((wn + nt * 16 + lrow) * RSTR + k0 + lko) * 2);
                #pragma unroll
                for (int ns = 0; ns < 8; ns++) {
                    int nt = ns >> 1, hf = ns & 1;
                    unsigned bl0 = bl[nt][hf], bl1 = bl[nt][hf + 2];
                    unsigned bh0 = bh[nt][hf], bh1 = bh[nt][hf + 2];
                    mma_f16(acc[0][ns], ah[0], bl0, bl1);
                    mma_f16(acc[1][ns], ah[1], bl0, bl1);
                    mma_f16(acc[0][ns], al[0], bh0, bh1);
                    mma_f16(acc[1][ns], al[1], bh0, bh1);
                }
            }
        }
        __syncthreads();  // convergence barrier (load-bearing, see R6 post-mortem)
        if (COMP && kt + 2 < KT) load_stage(s, kt + 2);
    }

    #pragma unroll
    for (int mf = 0; mf < 2; mf++) {
        int row = bm + wm + mf * 16 + g;
        #pragma unroll
        for (int nf = 0; nf < 8; nf++) {
            int col = bn + wn + nf * 8 + tg * 2;
            float b0v = bias[col], b1v = bias[col + 1];
            float v00 = acc[mf][nf][0] + b0v, v01 = acc[mf][nf][1] + b1v;
            float v10 = acc[mf][nf][2] + b0v, v11 = acc[mf][nf][3] + b1v;
            if (EPI == 1) {
                __half2 p0, p1;
                p0.x = __float2half_rn(gelu_f(v00)); p0.y = __float2half_rn(gelu_f(v01));
                p1.x = __float2half_rn(gelu_f(v10)); p1.y = __float2half_rn(gelu_f(v11));
                *(__half2*)&Chh[(size_t)row * N + col]       = p0;
                *(__half2*)&Chh[(size_t)(row + 8) * N + col] = p1;
            } else {
                *(float2*)&Cf[(size_t)row * N + col]       = make_float2(v00, v01);
                *(float2*)&Cf[(size_t)(row + 8) * N + col] = make_float2(v10, v11);
            }
        }
    }
}

// ---------------- fp16 dual-score flash attention ----------------
// Q frags hoisted to registers; P goes C-frag -> A-frag directly in registers
// (no smem round-trip; layouts match exactly for m16n8k16).
#define QS2 136
#define VS2 72
__global__ void __launch_bounds__(256) attn_h16(const __half* __restrict__ Qc,
                                                const __half* __restrict__ Qv,
                                                const __half* __restrict__ Kf,
                                                const __half* __restrict__ Vt,
                                                __half* __restrict__ outh) {
    extern __shared__ char smc[];
    const unsigned smb = sh_addr(smc);
    const unsigned qsb = smb;
    const unsigned ksb = qsb + 128 * QS2 * 2;
    const unsigned vsb = ksb + 2 * 64 * QS2 * 2;
    const int tid = threadIdx.x, warp = tid >> 5, lane = tid & 31;
    const int g = lane >> 2, tg = lane & 3;
    const int q0 = blockIdx.x * 128, h = blockIdx.y, b = blockIdx.z;
    const int bh = b * NH + h;

    const __half* qcb_ = Qc + ((size_t)(b * NQ + q0)) * DI + h * HD;
    const __half* qvb_ = Qv + ((size_t)(b * NQ + q0)) * DI + h * HD;
    #pragma unroll
    for (int i = 0; i < 8; i++) {
        int idx = tid + i * 256;
        int r = idx >> 4, c = idx & 15;
        const __half* src = (c < 8) ? (qcb_ + (size_t)r * DI + c * 8)
                                    : (qvb_ + (size_t)r * DI + (c - 8) * 8);
        cpa16(qsb + (unsigned)(r * QS2 + c * 8) * 2, src);
    }
    cpa_commit();

    const __half* kfb = Kf + (size_t)bh * NL * 128;
    const __half* vtb = Vt + (size_t)bh * 64 * NL;
    auto load_kv = [&](int s, int m0) {
        unsigned ks_ = ksb + s * (64 * QS2 * 2);
        unsigned vs_ = vsb + s * (64 * VS2 * 2);
        #pragma unroll
        for (int i = 0; i < 4; i++) {
            int idx = tid + i * 256;
            int r = idx >> 4, c = idx & 15;
            cpa16(ks_ + (unsigned)(r * QS2 + c * 8) * 2, kfb + (size_t)(m0 + r) * 128 + c * 8);
        }
        #pragma unroll
        for (int i = 0; i < 2; i++) {
            int idx = tid + i * 256;
            int r = idx >> 3, c = idx & 7;
            cpa16(vs_ + (unsigned)(r * VS2 + c * 8) * 2, vtb + (size_t)r * NL + m0 + c * 8);
        }
        cpa_commit();
    };
    load_kv(0, 0);
    load_kv(1, 64);

    const int wrow = warp * 16;
    const int lrow = lane & 15;
    const int lko = (lane >> 4) * 8;

    // hoist Q fragments (Q group complete once <=2 groups pending)
    asm volatile("cp.async.wait_group 2;" ::: "memory");
    __syncthreads();
    unsigned aq[8][4];
    #pragma unroll
    for (int kc2 = 0; kc2 < 8; kc2++)
        ldsm4(aq[kc2], qsb + (unsigned)((wrow + lrow) * QS2 + kc2 * 16 + lko) * 2);

    float m_[2] = {-1e30f, -1e30f}, l_[2] = {0.f, 0.f};
    float o[8][4];
    #pragma unroll
    for (int i = 0; i < 8; i++)
        #pragma unroll
        for (int j = 0; j < 4; j++) o[i][j] = 0.f;

    const int NIT = NL / 64;

    for (int it = 0; it < NIT; it++) {
        if (it < NIT - 1) asm volatile("cp.async.wait_group 1;" ::: "memory");
        else              asm volatile("cp.async.wait_group 0;" ::: "memory");
        __syncthreads();
        int s = it & 1;
        unsigned ksp = ksb + s * (64 * QS2 * 2);
        unsigned vsp = vsb + s * (64 * VS2 * 2);

        // S = Q K^T
        float sacc[8][4];
        #pragma unroll
        for (int i = 0; i < 8; i++)
            #pragma unroll
            for (int j = 0; j < 4; j++) sacc[i][j] = 0.f;
        #pragma unroll
        for (int kc2 = 0; kc2 < 8; kc2++) {
            int k0 = kc2 * 16;
            unsigned bh4[4][4];
            #pragma unroll
            for (int nt = 0; nt < 4; nt++)
                ldsm4(bh4[nt], ksp + (unsigned)((nt * 16 + lrow) * QS2 + k0 + lko) * 2);
            #pragma unroll
            for (int ns = 0; ns < 8; ns++) {
                int nt = ns >> 1, hf = ns & 1;
                mma_f16(sacc[ns], aq[kc2], bh4[nt][hf], bh4[nt][hf + 2]);
            }
        }

        // online softmax; P packed directly into A-fragments (registers)
        unsigned ph[8][2];  // [nf][rw]: half2(p_col0, p_col1)
        #pragma unroll
        for (int rw = 0; rw < 2; rw++) {
            float mx = -1e30f;
            #pragma unroll
            for (int nf = 0; nf < 8; nf++)
                mx = fmaxf(mx, fmaxf(sacc[nf][2 * rw], sacc[nf][2 * rw + 1]));
            mx = fmaxf(mx, __shfl_xor_sync(0xffffffffu, mx, 1));
            mx = fmaxf(mx, __shfl_xor_sync(0xffffffffu, mx, 2));
            float mn = fmaxf(m_[rw], mx);
            float corr = __expf(m_[rw] - mn);
            m_[rw] = mn;
            float sum = 0.f;
            #pragma unroll
            for (int nf = 0; nf < 8; nf++) {
                float p0 = __expf(sacc[nf][2 * rw] - mn);
                float p1 = __expf(sacc[nf][2 * rw + 1] - mn);
                sum += p0 + p1;
                ph[nf][rw] = pack_h2(p0, p1);
            }
            sum += __shfl_xor_sync(0xffffffffu, sum, 1);
            sum += __shfl_xor_sync(0xffffffffu, sum, 2);
            l_[rw] = l_[rw] * corr + sum;
            #pragma unroll
            for (int nf = 0; nf < 8; nf++) {
                o[nf][2 * rw]     *= corr;
                o[nf][2 * rw + 1] *= corr;
            }
        }

        // O += P V : A-frag a0=P[g][k0..k0+1], a1=P[g+8][..], a2=P[g][k0+8..], a3=P[g+8][k0+8..]
        #pragma unroll
        for (int kc2 = 0; kc2 < 4; kc2++) {
            int k0 = kc2 * 16;
            unsigned a[4];
            a[0] = ph[2 * kc2][0];
            a[1] = ph[2 * kc2][1];
            a[2] = ph[2 * kc2 + 1][0];
            a[3] = ph[2 * kc2 + 1][1];
            unsigned bv[4][4];
            #pragma unroll
            for (int nt = 0; nt < 4; nt++)
                ldsm4(bv[nt], vsp + (unsigned)((nt * 16 + lrow) * VS2 + k0 + lko) * 2);
            #pragma unroll
            for (int ns = 0; ns < 8; ns++) {
                int nt = ns >> 1, hf = ns & 1;
                mma_f16(o[ns], a, bv[nt][hf], bv[nt][hf + 2]);
            }
        }
        __syncthreads();
        if (it + 2 < NIT) load_kv(s, (it + 2) * 64);
    }

    #pragma unroll
    for (int rw = 0; rw < 2; rw++) {
        float inv = 1.f / l_[rw];
        int row = b * NQ + q0 + wrow + rw * 8 + g;
        #pragma unroll
        for (int nf = 0; nf < 8; nf++) {
            int col = h * HD + nf * 8 + tg * 2;
            __half2 hv;
            hv.x = __float2half_rn(o[nf][2 * rw] * inv);
            hv.y = __float2half_rn(o[nf][2 * rw + 1] * inv);
            *(__half2*)&outh[(size_t)row * DI + col] = hv;
        }
    }
}

// ---------------- host launcher ----------------
static void fill_ws(WsArgs& wa, const float** Ws, __half* wth, __half* wtl,
                    const int* Ks, const int* Ns, const int* offs, int n, int& total) {
    int acc0 = 0;
    for (int i = 0; i < n; i++) {
        wa.W[i] = Ws[i]; wa.th[i] = wth + offs[i]; wa.tl[i] = wtl + offs[i];
        wa.K[i] = Ks[i]; wa.N[i] = Ns[i];
        wa.start[i] = acc0;
        acc0 += (Ks[i] / 32) * (Ns[i] / 32);
    }
    for (int i = n; i < 9; i++) wa.start[i] = 0x7FFFFFFF;
    total = acc0;
}

extern "C" void kernel_launch(void* const* d_in, const int* in_sizes, int n_in,
                              void* d_out, int out_size) {
    const float* coords = (const float*)d_in[0];
    const float* values = (const float*)d_in[1];
    const float* Lv     = (const float*)d_in[2];
    const float* Lc     = (const float*)d_in[3];
    const float* lam    = (const float*)d_in[4];
    const float* lvn_g  = (const float*)d_in[5];
    const float* lvn_b  = (const float*)d_in[6];
    const float* lcn_g  = (const float*)d_in[7];
    const float* lcn_b  = (const float*)d_in[8];
    const float* ck_w   = (const float*)d_in[9];
    const float* ck_b   = (const float*)d_in[10];
    const float* ck_g   = (const float*)d_in[11];
    const float* cq_w   = (const float*)d_in[12];
    const float* cq_b   = (const float*)d_in[13];
    const float* cq_g   = (const float*)d_in[14];
    const float* vq_w   = (const float*)d_in[15];
    const float* vq_b   = (const float*)d_in[16];
    const float* vq_g   = (const float*)d_in[17];
    const float* vk_w   = (const float*)d_in[18];
    const float* vk_b   = (const float*)d_in[19];
    const float* op_w   = (const float*)d_in[20];
    const float* op_b   = (const float*)d_in[21];
    const float* oln_g  = (const float*)d_in[22];
    const float* oln_b  = (const float*)d_in[23];
    const float* m1_w   = (const float*)d_in[24];
    const float* m1_b   = (const float*)d_in[25];
    const float* m2_w   = (const float*)d_in[26];
    const float* m2_b   = (const float*)d_in[27];
    const float* m3_w   = (const float*)d_in[28];
    const float* m3_b   = (const float*)d_in[29];
    float* out = (float*)d_out;

    float *vkb, *kcb, *qvb, *qcb, *yb;
    cudaGetSymbolAddress((void**)&vkb, g_vk);
    cudaGetSymbolAddress((void**)&kcb, g_kc);
    cudaGetSymbolAddress((void**)&qvb, g_qv);
    cudaGetSymbolAddress((void**)&qcb, g_qc);
    cudaGetSymbolAddress((void**)&yb,  g_y);
    __half *sLvh, *sLch, *sLcl, *valh, *crdh, *crdl;
    __half *atth, *ybsh, *ybsl, *h1h, *h2h, *wth, *wtl;
    __half *qvh, *qch, *kf, *vt;
    cudaGetSymbolAddress((void**)&sLvh, g_sLv_h);
    cudaGetSymbolAddress((void**)&sLch, g_sLc_h); cudaGetSymbolAddress((void**)&sLcl, g_sLc_l);
    cudaGetSymbolAddress((void**)&valh, g_val_h);
    cudaGetSymbolAddress((void**)&crdh, g_crd_h); cudaGetSymbolAddress((void**)&crdl, g_crd_l);
    cudaGetSymbolAddress((void**)&atth, g_att_h);
    cudaGetSymbolAddress((void**)&ybsh, g_ybs_h); cudaGetSymbolAddress((void**)&ybsl, g_ybs_l);
    cudaGetSymbolAddress((void**)&h1h,  g_h1_h);
    cudaGetSymbolAddress((void**)&h2h,  g_h2_h);
    cudaGetSymbolAddress((void**)&wth,  g_wth);   cudaGetSymbolAddress((void**)&wtl,  g_wtl);
    cudaGetSymbolAddress((void**)&qvh,  g_qvh);   cudaGetSymbolAddress((void**)&qch,  g_qch);
    cudaGetSymbolAddress((void**)&kf,   g_kf);    cudaGetSymbolAddress((void**)&vt,   g_vt);

    const int BNL = BATCH * NL;
    const int BNQ = BATCH * NQ;
    const int GSMC = 2 * 4 * PLANE_B;  // 81920
    const int GSM1 = 4 * 2 * PLANE_B;  // 81920
    const int ATTN_SMEM = 128 * QS2 * 2 + 2 * 64 * QS2 * 2 + 2 * 64 * VS2 * 2; // 88064
    cudaFuncSetAttribute((const void*)gemm_h<0, true>,  cudaFuncAttributeMaxDynamicSharedMemorySize, GSMC);
    cudaFuncSetAttribute((const void*)gemm_h<0, false>, cudaFuncAttributeMaxDynamicSharedMemorySize, GSM1);
    cudaFuncSetAttribute((const void*)gemm_h<1, false>, cudaFuncAttributeMaxDynamicSharedMemorySize, GSM1);
    cudaFuncSetAttribute(attn_h16, cudaFuncAttributeMaxDynamicSharedMemorySize, ATTN_SMEM);

    // ONE extra stream only (R16 lesson: >1 extra stream allocates device mem
    // during capture and trips the harness guard)
    cudaStream_t s1;
    cudaStreamCreateWithFlags(&s1, cudaStreamNonBlocking);
    cudaEvent_t eF, eW, eK, eW2;
    cudaEventCreateWithFlags(&eF,  cudaEventDisableTiming);
    cudaEventCreateWithFlags(&eW,  cudaEventDisableTiming);
    cudaEventCreateWithFlags(&eK,  cudaEventDisableTiming);
    cudaEventCreateWithFlags(&eW2, cudaEventDisableTiming);

    // fork: latent/K branch starts immediately
    cudaEventRecord(eF, 0);
    cudaStreamWaitEvent(s1, eF, 0);
    layernorm_t<false><<<BNL, 256, 0, s1>>>(Lv, lvn_g, lvn_b, sLvh, (__half*)0, DV, 1e-5f);
    layernorm_t<true><<<BNL, 128, 0, s1>>>(Lc, lcn_g, lcn_b, sLch, sLcl, DC, 1e-5f);

    // weight split PHASE 1 on main: projection weights
    {
        WsArgs wa; int tot;
        const float* Ws[4] = {ck_w, cq_w, vq_w, vk_w};
        int Ks[4] = {DC, DC, DV, DV};
        int Ns[4] = {DI, DI, DI, 2 * DI};
        int offs[4] = {OFF_CKW, OFF_CQW, OFF_VQW, OFF_VKW};
        fill_ws(wa, Ws, wth, wtl, Ks, Ns, offs, 4, tot);
        wtsplit_all<<<tot, dim3(32, 8)>>>(wa);
    }
    cudaEventRecord(eW, 0);

    // latent/K branch on s1
    cudaStreamWaitEvent(s1, eW, 0);
    gemm_h<0, false><<<dim3(8, 32), 256, GSM1, s1>>>(sLvh, (__half*)0, wth + OFF_VKW, (__half*)0,
                                                     vk_b, vkb, (__half*)0, BNL, DV, 2 * DI);
    gemm_h<0, true><<<dim3(4, 32), 256, GSMC, s1>>>(sLch, sLcl, wth + OFF_CKW, wtl + OFF_CKW,
                                                    ck_b, kcb, (__half*)0, BNL, DC, DI);
    rmsnorm_kernel<<<BNL, 256, 0, s1>>>(kcb, ck_g, DI, 1e-6f, 1.0f);
    kcomb_kernel<<<dim3(NL, BATCH), 256, 0, s1>>>(kcb, vkb, lam, kf);
    vtrans_kernel<<<dim3(NL/32, 2, BATCH*NH), dim3(32, 8), 0, s1>>>(vkb, vt);
    cudaEventRecord(eK, s1);

    // weight split PHASE 2 on s1 — overlaps attention on main
    {
        WsArgs wa; int tot;
        const float* Ws[4] = {op_w, m1_w, m2_w, m3_w};
        int Ks[4] = {DI, DV, DF, DF};
        int Ns[4] = {DV, DF, DF, DV};
        int offs[4] = {OFF_OPW, OFF_M1W, OFF_M2W, OFF_M3W};
        fill_ws(wa, Ws, wth, wtl, Ks, Ns, offs, 4, tot);
        wtsplit_all<<<tot, dim3(32, 8), 0, s1>>>(wa);
    }
    cudaEventRecord(eW2, s1);

    // q branch on main stream
    convert_h<<<BNQ * DV / 4 / 256, 256>>>(values, valh, BNQ * DV / 4);
    split_copy_h<<<BNQ * DC / 4 / 256, 256>>>(coords, crdh, crdl, BNQ * DC / 4);
    gemm_h<0, false><<<dim3(4, 128), 256, GSM1>>>(valh, (__half*)0, wth + OFF_VQW, (__half*)0,
                                                  vq_b, qvb, (__half*)0, BNQ, DV, DI);
    gemm_h<0, true><<<dim3(4, 128), 256, GSMC>>>(crdh, crdl, wth + OFF_CQW, wtl + OFF_CQW,
                                                 cq_b, qcb, (__half*)0, BNQ, DC, DI);
    rmsnorm_h<<<BNQ, 256>>>(qvb, vq_g, qvh, DI, 1e-6f, 0.125f);
    rmsnorm_h<<<BNQ, 256>>>(qcb, cq_g, qch, DI, 1e-6f, 0.125f);

    // join K branch, attention
    cudaStreamWaitEvent(0, eK, 0);
    attn_h16<<<dim3(NQ/128, NH, BATCH), 256, ATTN_SMEM>>>(qch, qvh, kf, vt, atth);

    // join phase-2 weights, MLP tail
    cudaStreamWaitEvent(0, eW2, 0);
    gemm_h<0, false><<<dim3(4, 128), 256, GSM1>>>(atth, (__half*)0, wth + OFF_OPW, (__half*)0,
                                                  op_b, yb, (__half*)0, BNQ, DI, DV);
    layernorm_t<true><<<BNQ, 256>>>(yb, oln_g, oln_b, ybsh, ybsl, DV, 1e-5f);
    gemm_h<1, false><<<dim3(16, 128), 256, GSM1>>>(ybsh, (__half*)0, wth + OFF_M1W, (__half*)0,
                                                   m1_b, (float*)0, h1h, BNQ, DV, DF);
    gemm_h<1, false><<<dim3(16, 128), 256, GSM1>>>(h1h, (__half*)0, wth + OFF_M2W, (__half*)0,
                                                   m2_b, (float*)0, h2h, BNQ, DF, DF);
    gemm_h<0, false><<<dim3(4, 128), 256, GSM1>>>(h2h, (__half*)0, wth + OFF_M3W, (__half*)0,
                                                  m3_b, out, (__half*)0, BNQ, DF, DV);
}